// round 5
// baseline (speedup 1.0000x reference)
#include <cuda_runtime.h>

// Problem constants
#define D_MODEL 2048
#define S_LEN   2048
#define BATCH   2
#define NHEADS  16
#define HDIM    128
#define NROWS   (BATCH * S_LEN)          // 4096

// GEMM tiling
#define BM 128
#define BN 128
#define BK 16
#define ASTR 132                          // padded smem row stride (floats)

// Flash attention tiling
#define TQ 64
#define TK 64
#define KSTR 68                           // K-transposed smem stride
#define PSTR 65                           // score tile smem stride
#define FLASH_SMEM_FLOATS (TQ*HDIM + HDIM*KSTR + TK*HDIM + TQ*PSTR + 3*TQ)
#define FLASH_SMEM_BYTES  (FLASH_SMEM_FLOATS * 4)

// Scratch (device globals: allocation-free rule)
__device__ float g_q[(size_t)BATCH * NHEADS * S_LEN * HDIM];   // [b][h][s][dh]
__device__ float g_k[(size_t)BATCH * NHEADS * S_LEN * HDIM];
__device__ float g_v[(size_t)BATCH * NHEADS * S_LEN * HDIM];
__device__ float g_attn[(size_t)NROWS * D_MODEL];              // [b*s][h*128+dh]

// ---------------------------------------------------------------------------
// Shared GEMM core: C_tile(128x128) += A[row0.., :] @ B[col0.., :]^T
// A: [M, 2048] row-major, Bw: [N, 2048] row-major (both K-contiguous).
// 256 threads as 16x16; thread (tx,ty) owns rows ty*8..+7,
// cols {tx*4..+3} and {64+tx*4..+3}  (split-column microtile: conflict-free LDS.128)
// ---------------------------------------------------------------------------
__device__ __forceinline__ void gemm_core(const float* __restrict__ A,
                                          const float* __restrict__ Bw,
                                          int row0, int col0,
                                          float acc[8][8]) {
    __shared__ __align__(16) float As[BK * ASTR];   // As[k][m]
    __shared__ __align__(16) float Bs[BK * ASTR];   // Bs[k][n]
    const int tid = threadIdx.x;
    const int tx = tid & 15;
    const int ty = tid >> 4;
    const int lr = tid >> 2;          // 0..63
    const int lk = (tid & 3) << 2;    // 0,4,8,12

    for (int k0 = 0; k0 < D_MODEL; k0 += BK) {
        #pragma unroll
        for (int h = 0; h < 2; h++) {
            const int r = lr + h * 64;
            float4 av = *(const float4*)(A + (size_t)(row0 + r) * D_MODEL + k0 + lk);
            As[(lk + 0) * ASTR + r] = av.x;
            As[(lk + 1) * ASTR + r] = av.y;
            As[(lk + 2) * ASTR + r] = av.z;
            As[(lk + 3) * ASTR + r] = av.w;
            float4 bv = *(const float4*)(Bw + (size_t)(col0 + r) * D_MODEL + k0 + lk);
            Bs[(lk + 0) * ASTR + r] = bv.x;
            Bs[(lk + 1) * ASTR + r] = bv.y;
            Bs[(lk + 2) * ASTR + r] = bv.z;
            Bs[(lk + 3) * ASTR + r] = bv.w;
        }
        __syncthreads();
        #pragma unroll
        for (int kk = 0; kk < BK; kk++) {
            float ar[8], br[8];
            *(float4*)(ar)     = *(const float4*)(As + kk * ASTR + ty * 8);
            *(float4*)(ar + 4) = *(const float4*)(As + kk * ASTR + ty * 8 + 4);
            *(float4*)(br)     = *(const float4*)(Bs + kk * ASTR + tx * 4);
            *(float4*)(br + 4) = *(const float4*)(Bs + kk * ASTR + 64 + tx * 4);
            #pragma unroll
            for (int i = 0; i < 8; i++)
                #pragma unroll
                for (int j = 0; j < 8; j++)
                    acc[i][j] = fmaf(ar[i], br[j], acc[i][j]);
        }
        __syncthreads();
    }
}

// ---------------------------------------------------------------------------
// QKV projection: z in {0,1,2} selects {Wq,Wk,Wv} -> {g_q,g_k,g_v}
// Epilogue scatters into [b][h][s][dh] (one BN=128 column block == one head).
// ---------------------------------------------------------------------------
__global__ __launch_bounds__(256) void qkv_gemm_kernel(
        const float* __restrict__ x,
        const float* __restrict__ wq,
        const float* __restrict__ wk,
        const float* __restrict__ wv) {
    float acc[8][8];
    #pragma unroll
    for (int i = 0; i < 8; i++)
        #pragma unroll
        for (int j = 0; j < 8; j++) acc[i][j] = 0.f;

    const float* W = (blockIdx.z == 0) ? wq : (blockIdx.z == 1) ? wk : wv;
    float* out     = (blockIdx.z == 0) ? g_q : (blockIdx.z == 1) ? g_k : g_v;

    const int row0 = blockIdx.y * BM;
    const int col0 = blockIdx.x * BN;
    gemm_core(x, W, row0, col0, acc);

    const int tx = threadIdx.x & 15, ty = threadIdx.x >> 4;
    const int hh  = col0 >> 7;      // head index (BN == HDIM)
    const int dh0 = tx * 4;
    #pragma unroll
    for (int i = 0; i < 8; i++) {
        const int gr = row0 + ty * 8 + i;
        const int b = gr >> 11;           // / S_LEN
        const int s = gr & 2047;
        float* dst = out + ((size_t)((b * NHEADS + hh) * S_LEN + s) << 7);
        *(float4*)(dst + dh0)      = make_float4(acc[i][0], acc[i][1], acc[i][2], acc[i][3]);
        *(float4*)(dst + 64 + dh0) = make_float4(acc[i][4], acc[i][5], acc[i][6], acc[i][7]);
    }
}

// ---------------------------------------------------------------------------
// Output projection: d_out = g_attn @ Wo^T
// ---------------------------------------------------------------------------
__global__ __launch_bounds__(256) void out_gemm_kernel(
        const float* __restrict__ wo, float* __restrict__ C) {
    float acc[8][8];
    #pragma unroll
    for (int i = 0; i < 8; i++)
        #pragma unroll
        for (int j = 0; j < 8; j++) acc[i][j] = 0.f;

    const int row0 = blockIdx.y * BM;
    const int col0 = blockIdx.x * BN;
    gemm_core(g_attn, wo, row0, col0, acc);

    const int tx = threadIdx.x & 15, ty = threadIdx.x >> 4;
    #pragma unroll
    for (int i = 0; i < 8; i++) {
        const int gr = row0 + ty * 8 + i;
        float* dst = C + (size_t)gr * D_MODEL + col0;
        *(float4*)(dst + tx * 4)      = make_float4(acc[i][0], acc[i][1], acc[i][2], acc[i][3]);
        *(float4*)(dst + 64 + tx * 4) = make_float4(acc[i][4], acc[i][5], acc[i][6], acc[i][7]);
    }
}

// ---------------------------------------------------------------------------
// Causal flash attention. Block = (q-tile of 64, one (b,h)). 256 threads.
// Online softmax with running (m, l); O accumulator 4x8 per thread.
// ---------------------------------------------------------------------------
__global__ __launch_bounds__(256) void flash_kernel() {
    extern __shared__ __align__(16) float sm[];
    float* Qs   = sm;                    // [64][128]
    float* Ks   = Qs + TQ * HDIM;        // transposed: [128][KSTR]
    float* Vs   = Ks + HDIM * KSTR;      // [64][128]
    float* Ps   = Vs + TK * HDIM;        // [64][PSTR]
    float* mrow = Ps + TQ * PSTR;        // [64]
    float* lrow = mrow + TQ;             // [64]
    float* rsc  = lrow + TQ;             // [64]

    const int tid = threadIdx.x;
    const int tx = tid & 15, ty = tid >> 4;
    const int q0 = blockIdx.x * TQ;
    const int bh = blockIdx.y;           // b*16 + h
    const float* Qp = g_q + (size_t)bh * S_LEN * HDIM;
    const float* Kp = g_k + (size_t)bh * S_LEN * HDIM;
    const float* Vp = g_v + (size_t)bh * S_LEN * HDIM;
    const float NEG_INF = __int_as_float(0xff800000);

    // Load Q tile (float4 granularity: 2048 chunks)
    for (int p = tid; p < TQ * HDIM / 4; p += 256) {
        const int r = p >> 5, c = (p & 31) << 2;
        *(float4*)(Qs + r * HDIM + c) = *(const float4*)(Qp + (size_t)(q0 + r) * HDIM + c);
    }
    if (tid < TQ) { mrow[tid] = NEG_INF; lrow[tid] = 0.f; }

    float acc[4][8];
    #pragma unroll
    for (int r = 0; r < 4; r++)
        #pragma unroll
        for (int j = 0; j < 8; j++) acc[r][j] = 0.f;

    const int ntiles = blockIdx.x + 1;       // causal: k0 <= q0
    for (int t = 0; t < ntiles; t++) {
        const int k0 = t * TK;
        __syncthreads();                     // prev iter done with Ks/Vs/Ps
        for (int p = tid; p < TK * HDIM / 4; p += 256) {
            const int r = p >> 5, c = (p & 31) << 2;
            float4 kv = *(const float4*)(Kp + (size_t)(k0 + r) * HDIM + c);
            Ks[(c + 0) * KSTR + r] = kv.x;
            Ks[(c + 1) * KSTR + r] = kv.y;
            Ks[(c + 2) * KSTR + r] = kv.z;
            Ks[(c + 3) * KSTR + r] = kv.w;
            *(float4*)(Vs + r * HDIM + c) = *(const float4*)(Vp + (size_t)(k0 + r) * HDIM + c);
        }
        __syncthreads();

        // Scores: thread owns q rows ty*4..+3, k cols tx*4..+3
        float s_[4][4];
        #pragma unroll
        for (int r = 0; r < 4; r++)
            #pragma unroll
            for (int c = 0; c < 4; c++) s_[r][c] = 0.f;

        #pragma unroll 2
        for (int d = 0; d < HDIM; d += 4) {
            float kv[4][4];
            #pragma unroll
            for (int dd = 0; dd < 4; dd++) {
                float4 kf = *(const float4*)(Ks + (d + dd) * KSTR + tx * 4);
                kv[dd][0] = kf.x; kv[dd][1] = kf.y; kv[dd][2] = kf.z; kv[dd][3] = kf.w;
            }
            #pragma unroll
            for (int r = 0; r < 4; r++) {
                float4 qf = *(const float4*)(Qs + (ty * 4 + r) * HDIM + d);
                float qv[4] = {qf.x, qf.y, qf.z, qf.w};
                #pragma unroll
                for (int dd = 0; dd < 4; dd++)
                    #pragma unroll
                    for (int c = 0; c < 4; c++)
                        s_[r][c] = fmaf(qv[dd], kv[dd][c], s_[r][c]);
            }
        }

        const float qsc = 0.08838834764831845f;   // 1/sqrt(128)
        if (t == ntiles - 1) {
            #pragma unroll
            for (int r = 0; r < 4; r++)
                #pragma unroll
                for (int c = 0; c < 4; c++) {
                    const int gq_ = q0 + ty * 4 + r;
                    const int gk_ = k0 + tx * 4 + c;
                    Ps[(ty * 4 + r) * PSTR + tx * 4 + c] =
                        (gk_ > gq_) ? NEG_INF : s_[r][c] * qsc;
                }
        } else {
            #pragma unroll
            for (int r = 0; r < 4; r++)
                #pragma unroll
                for (int c = 0; c < 4; c++)
                    Ps[(ty * 4 + r) * PSTR + tx * 4 + c] = s_[r][c] * qsc;
        }
        __syncthreads();

        // Online softmax: one thread per row
        if (tid < TQ) {
            const float mo = mrow[tid];
            float mx = mo;
            #pragma unroll 4
            for (int k = 0; k < TK; k++) mx = fmaxf(mx, Ps[tid * PSTR + k]);
            const float scl = __expf(mo - mx);       // 0 when mo == -inf
            float l = lrow[tid] * scl;
            #pragma unroll 4
            for (int k = 0; k < TK; k++) {
                const float e = __expf(Ps[tid * PSTR + k] - mx);
                Ps[tid * PSTR + k] = e;
                l += e;
            }
            mrow[tid] = mx; lrow[tid] = l; rsc[tid] = scl;
        }
        __syncthreads();

        // Rescale O and accumulate P @ V
        float rs[4];
        #pragma unroll
        for (int r = 0; r < 4; r++) rs[r] = rsc[ty * 4 + r];
        #pragma unroll
        for (int r = 0; r < 4; r++)
            #pragma unroll
            for (int j = 0; j < 8; j++) acc[r][j] *= rs[r];

        #pragma unroll 2
        for (int k = 0; k < TK; k++) {
            float pv[4];
            #pragma unroll
            for (int r = 0; r < 4; r++) pv[r] = Ps[(ty * 4 + r) * PSTR + k];
            const float4 v0 = *(const float4*)(Vs + k * HDIM + tx * 4);
            const float4 v1 = *(const float4*)(Vs + k * HDIM + 64 + tx * 4);
            #pragma unroll
            for (int r = 0; r < 4; r++) {
                acc[r][0] = fmaf(pv[r], v0.x, acc[r][0]);
                acc[r][1] = fmaf(pv[r], v0.y, acc[r][1]);
                acc[r][2] = fmaf(pv[r], v0.z, acc[r][2]);
                acc[r][3] = fmaf(pv[r], v0.w, acc[r][3]);
                acc[r][4] = fmaf(pv[r], v1.x, acc[r][4]);
                acc[r][5] = fmaf(pv[r], v1.y, acc[r][5]);
                acc[r][6] = fmaf(pv[r], v1.z, acc[r][6]);
                acc[r][7] = fmaf(pv[r], v1.w, acc[r][7]);
            }
        }
    }

    // Epilogue: normalize and write [b][s][h*128+dh]
    const int b = bh >> 4, h = bh & 15;
    #pragma unroll
    for (int r = 0; r < 4; r++) {
        const int s = q0 + ty * 4 + r;
        const float inv = 1.0f / lrow[ty * 4 + r];
        float* dst = g_attn + (size_t)(b * S_LEN + s) * D_MODEL + h * HDIM;
        *(float4*)(dst + tx * 4) =
            make_float4(acc[r][0] * inv, acc[r][1] * inv, acc[r][2] * inv, acc[r][3] * inv);
        *(float4*)(dst + 64 + tx * 4) =
            make_float4(acc[r][4] * inv, acc[r][5] * inv, acc[r][6] * inv, acc[r][7] * inv);
    }
}

// ---------------------------------------------------------------------------
extern "C" void kernel_launch(void* const* d_in, const int* in_sizes, int n_in,
                              void* d_out, int out_size) {
    const float* x  = (const float*)d_in[0];
    const float* wq = (const float*)d_in[1];
    const float* wk = (const float*)d_in[2];
    const float* wv = (const float*)d_in[3];
    const float* wo = (const float*)d_in[4];
    float* out = (float*)d_out;

    cudaFuncSetAttribute(flash_kernel,
                         cudaFuncAttributeMaxDynamicSharedMemorySize,
                         FLASH_SMEM_BYTES);

    qkv_gemm_kernel<<<dim3(D_MODEL / BN, NROWS / BM, 3), 256>>>(x, wq, wk, wv);
    flash_kernel<<<dim3(S_LEN / TQ, BATCH * NHEADS), 256, FLASH_SMEM_BYTES>>>();
    out_gemm_kernel<<<dim3(D_MODEL / BN, NROWS / BM), 256>>>(wo, out);
}

// round 8
// speedup vs baseline: 2.1013x; 2.1013x over previous
#include <cuda_runtime.h>
#include <cuda_bf16.h>
#include <cstdint>

// Problem constants
#define D_MODEL 2048
#define S_LEN   2048
#define BATCH   2
#define NHEADS  16
#define HDIM    128
#define NROWS   (BATCH * S_LEN)          // 4096
#define X_ELEMS ((size_t)NROWS * D_MODEL)        // 8388608
#define W_ELEMS ((size_t)D_MODEL * D_MODEL)      // 4194304

// Arch feature gate: tcgen05 only exists when compiling for sm_103a.
#if defined(__CUDA_ARCH_FEAT_SM103_ALL)
#define USE_TCGEN05 1
#else
#define USE_TCGEN05 0
#endif

// ------------------------- scratch (device globals) -------------------------
__device__ float g_q[(size_t)BATCH * NHEADS * S_LEN * HDIM];   // [b][h][s][dh]
__device__ float g_k[(size_t)BATCH * NHEADS * S_LEN * HDIM];
__device__ float g_v[(size_t)BATCH * NHEADS * S_LEN * HDIM];
__device__ float g_attn[(size_t)NROWS * D_MODEL];              // [b*s][h*128+dh]

__device__ __nv_bfloat16 g_xh[X_ELEMS], g_xl[X_ELEMS];
__device__ __nv_bfloat16 g_wh[4 * W_ELEMS], g_wl[4 * W_ELEMS]; // q,k,v,o
__device__ __nv_bfloat16 g_ah[X_ELEMS], g_al[X_ELEMS];

// ------------------------- common helpers ----------------------------------
__device__ __forceinline__ uint32_t smem_u32(const void* p) {
    uint32_t a;
    asm("{ .reg .u64 t; cvta.to.shared.u64 t, %1; cvt.u32.u64 %0, t; }"
        : "=r"(a) : "l"(p));
    return a;
}

// Dynamic smem request (covers both paths):
// mma.sync path: 2 stages x 4 matrices x (128 rows x 40 bf16) = 81920 B
// tcgen05 path : 1024 hdr + 4 x 16384 = 66560 B
#define GEMM_SMEM_BYTES 81920

#if USE_TCGEN05
// ======================= tcgen05 path (sm_103a only) ========================
__device__ __forceinline__ uint32_t elect_one_pred() {
    uint32_t pred;
    asm volatile("{\n\t.reg .pred p;\n\telect.sync _|p, 0xFFFFFFFF;\n\t"
                 "selp.b32 %0, 1, 0, p;\n\t}" : "=r"(pred));
    return pred;
}

#define TCGEN05_ALLOC(smem_addr, nCols) \
    asm volatile("tcgen05.alloc.cta_group::1.sync.aligned.shared::cta.b32 [%0], %1;" \
                 :: "r"((uint32_t)(smem_addr)), "r"((uint32_t)(nCols)) : "memory")
#define TCGEN05_DEALLOC(tmem_addr, nCols) \
    asm volatile("tcgen05.dealloc.cta_group::1.sync.aligned.b32 %0, %1;" \
                 :: "r"(tmem_addr), "r"((uint32_t)(nCols)))
#define TCGEN05_RELINQUISH() \
    asm volatile("tcgen05.relinquish_alloc_permit.cta_group::1.sync.aligned;")
#define TCGEN05_COMMIT(mbar) \
    asm volatile("tcgen05.commit.cta_group::1.mbarrier::arrive::one.shared::cluster.b64 [%0];" \
                 :: "r"((uint32_t)(mbar)) : "memory")
#define TCGEN05_FENCE_BEFORE() asm volatile("tcgen05.fence::before_thread_sync;" ::: "memory")
#define TCGEN05_FENCE_AFTER()  asm volatile("tcgen05.fence::after_thread_sync;" ::: "memory")
#define TCGEN05_WAIT_LD()      asm volatile("tcgen05.wait::ld.sync.aligned;" ::: "memory")
#define FENCE_PROXY_ASYNC()    asm volatile("fence.proxy.async.shared::cta;" ::: "memory")

#define MBARRIER_INIT(mbar, cnt) \
    asm volatile("mbarrier.init.shared.b64 [%0], %1;" \
                 :: "r"((uint32_t)(mbar)), "r"((uint32_t)(cnt)) : "memory")
#define MBARRIER_INVAL(mbar) \
    asm volatile("mbarrier.inval.shared.b64 [%0];" :: "r"((uint32_t)(mbar)) : "memory")
#define MBARRIER_WAIT_PARITY(mbar_smem_addr, phase_parity) do { \
    uint32_t _mbar = (uint32_t)(mbar_smem_addr); \
    uint32_t _parity = (uint32_t)(phase_parity); \
    uint32_t _done; \
    asm volatile("{\n\t.reg .pred p;\n\t" \
        "mbarrier.try_wait.parity.acquire.cta.shared::cta.b64 p, [%1], %2;\n\t" \
        "selp.b32 %0, 1, 0, p;\n\t}" \
        : "=r"(_done) : "r"(_mbar), "r"(_parity) : "memory"); \
    if (!_done) { \
        asm volatile("{\n\t.reg .pred P1;\n\t" \
            "WAIT_LOOP_%=:\n\t" \
            "mbarrier.try_wait.parity.acquire.cta.shared::cta.b64 P1, [%0], %1, 0x989680;\n\t" \
            "@P1 bra.uni WAIT_DONE_%=;\n\t" \
            "bra.uni WAIT_LOOP_%=;\n\t" \
            "WAIT_DONE_%=:\n\t}" \
            :: "r"(_mbar), "r"(_parity) : "memory"); \
    } \
} while (0)

#define TCGEN05_LD_32X32B_X32(r, tmem_addr) \
    asm volatile("tcgen05.ld.sync.aligned.32x32b.x32.b32 " \
        "{%0, %1, %2, %3, %4, %5, %6, %7, " \
        " %8, %9, %10, %11, %12, %13, %14, %15, " \
        " %16, %17, %18, %19, %20, %21, %22, %23, " \
        " %24, %25, %26, %27, %28, %29, %30, %31}, [%32];" \
        : "=r"((r)[0]),  "=r"((r)[1]),  "=r"((r)[2]),  "=r"((r)[3]), \
          "=r"((r)[4]),  "=r"((r)[5]),  "=r"((r)[6]),  "=r"((r)[7]), \
          "=r"((r)[8]),  "=r"((r)[9]),  "=r"((r)[10]), "=r"((r)[11]), \
          "=r"((r)[12]), "=r"((r)[13]), "=r"((r)[14]), "=r"((r)[15]), \
          "=r"((r)[16]), "=r"((r)[17]), "=r"((r)[18]), "=r"((r)[19]), \
          "=r"((r)[20]), "=r"((r)[21]), "=r"((r)[22]), "=r"((r)[23]), \
          "=r"((r)[24]), "=r"((r)[25]), "=r"((r)[26]), "=r"((r)[27]), \
          "=r"((r)[28]), "=r"((r)[29]), "=r"((r)[30]), "=r"((r)[31]) \
        : "r"(tmem_addr))

__device__ __forceinline__ void mma_bf16_ss(uint32_t d_tmem, uint64_t a_desc,
                                            uint64_t b_desc, uint32_t idesc,
                                            uint32_t enable) {
    asm volatile("{\n\t.reg .pred p;\n\tsetp.ne.u32 p, %5, 0;\n\t"
        "tcgen05.mma.cta_group::1.kind::f16 [%0], %1, %2, %3, {%4, %4, %4, %4}, p;\n\t}"
        :: "r"(d_tmem), "l"(a_desc), "l"(b_desc), "r"(idesc), "r"(0u), "r"(enable)
        : "memory");
}

static constexpr uint64_t SMEM_DESC_BASE_SW128 =
    (uint64_t(2) << 61) | (uint64_t(1) << 46) | (uint64_t(64) << 32) | (uint64_t(1) << 16);
#define MAKE_SMEM_DESC(a) (SMEM_DESC_BASE_SW128 | ((uint64_t)((a) >> 4) & 0x3FFF))
#define SW128(o) ((o) ^ (((o) >> 3) & 0x70))
#define GEMM_IDESC (0x8200490u)   // F32 acc, bf16 x bf16, M=128, N=128

#define OFF_AH 1024
#define OFF_AL (OFF_AH + 16384)
#define OFF_BH (OFF_AL + 16384)
#define OFF_BL (OFF_BH + 16384)

// 256-thread tcgen05 GEMM core: D(128x128) = A @ B^T, bf16 hi/lo split.
__device__ __forceinline__ uint32_t gemm_tile_tc(
        const __nv_bfloat16* __restrict__ Ah, const __nv_bfloat16* __restrict__ Al,
        const __nv_bfloat16* __restrict__ Bh, const __nv_bfloat16* __restrict__ Bl,
        char* smem, uint32_t sb) {
    const int tid = threadIdx.x;
    const int wid = tid >> 5;

    if (tid == 0) MBARRIER_INIT(sb + 8, 1);
    if (wid == 0) { TCGEN05_ALLOC(sb + 0, 128); TCGEN05_RELINQUISH(); }
    __syncthreads();
    uint32_t tmem;
    asm volatile("ld.shared.b32 %0, [%1];" : "=r"(tmem) : "r"(sb + 0));

    for (int c = 0; c < D_MODEL / 64; c++) {
        const int k0 = c * 64;
        #pragma unroll
        for (int it = 0; it < 4; it++) {
            const int p = tid + it * 256;           // 0..1023
            const int r = p >> 3;
            const size_t go = (size_t)r * D_MODEL + k0 + (p & 7) * 8;
            uint4 vah = *(const uint4*)(Ah + go);
            uint4 val = *(const uint4*)(Al + go);
            uint4 vbh = *(const uint4*)(Bh + go);
            uint4 vbl = *(const uint4*)(Bl + go);
            const uint32_t so = SW128((uint32_t)(r * 128 + (p & 7) * 16));
            *(uint4*)(smem + OFF_AH + so) = vah;
            *(uint4*)(smem + OFF_AL + so) = val;
            *(uint4*)(smem + OFF_BH + so) = vbh;
            *(uint4*)(smem + OFF_BL + so) = vbl;
        }
        FENCE_PROXY_ASYNC();
        __syncthreads();

        if (wid == 0) {
            if (elect_one_pred()) {
                const uint64_t dah = MAKE_SMEM_DESC(sb + OFF_AH);
                const uint64_t dal = MAKE_SMEM_DESC(sb + OFF_AL);
                const uint64_t dbh = MAKE_SMEM_DESC(sb + OFF_BH);
                const uint64_t dbl = MAKE_SMEM_DESC(sb + OFF_BL);
                #pragma unroll
                for (int ks = 0; ks < 4; ks++)
                    mma_bf16_ss(tmem, dah + ks * 2, dbh + ks * 2, GEMM_IDESC,
                                (c == 0 && ks == 0) ? 0u : 1u);
                #pragma unroll
                for (int ks = 0; ks < 4; ks++)
                    mma_bf16_ss(tmem, dal + ks * 2, dbh + ks * 2, GEMM_IDESC, 1u);
                #pragma unroll
                for (int ks = 0; ks < 4; ks++)
                    mma_bf16_ss(tmem, dah + ks * 2, dbl + ks * 2, GEMM_IDESC, 1u);
                TCGEN05_COMMIT(sb + 8);
            }
        }
        MBARRIER_WAIT_PARITY(sb + 8, c & 1);
    }
    TCGEN05_FENCE_AFTER();
    return tmem;
}
#endif // USE_TCGEN05

// ===================== mma.sync fallback path (sm_103) ======================
// 128x128 CTA tile, 256 threads = 8 warps in 2(m) x 4(n); warp tile 64x32.
// bf16 hi/lo split: D += Ah*Bh + Al*Bh + Ah*Bl. cp.async double-buffered K=32.
#define MM_SA     40                         // padded smem stride (bf16 elems)
#define MM_MAT    10240                      // bytes per 128x40 bf16 matrix
#define MM_STAGE  40960                      // 4 matrices per stage

__device__ __forceinline__ void cp_async16(uint32_t s, const void* g) {
    asm volatile("cp.async.ca.shared.global [%0], [%1], 16;"
                 :: "r"(s), "l"(g) : "memory");
}
#define CP_COMMIT() asm volatile("cp.async.commit_group;" ::: "memory")
#define CP_WAIT1()  asm volatile("cp.async.wait_group 1;" ::: "memory")

__device__ __forceinline__ void ldsm_x4(uint32_t* r, uint32_t addr) {
    asm volatile("ldmatrix.sync.aligned.m8n8.x4.shared.b16 {%0,%1,%2,%3}, [%4];"
                 : "=r"(r[0]), "=r"(r[1]), "=r"(r[2]), "=r"(r[3]) : "r"(addr));
}
__device__ __forceinline__ void ldsm_x2(uint32_t* r, uint32_t addr) {
    asm volatile("ldmatrix.sync.aligned.m8n8.x2.shared.b16 {%0,%1}, [%2];"
                 : "=r"(r[0]), "=r"(r[1]) : "r"(addr));
}
__device__ __forceinline__ void mma16816(float* d, const uint32_t* a, const uint32_t* b) {
    asm volatile("mma.sync.aligned.m16n8k16.row.col.f32.bf16.bf16.f32 "
        "{%0,%1,%2,%3}, {%4,%5,%6,%7}, {%8,%9}, {%0,%1,%2,%3};"
        : "+f"(d[0]), "+f"(d[1]), "+f"(d[2]), "+f"(d[3])
        : "r"(a[0]), "r"(a[1]), "r"(a[2]), "r"(a[3]), "r"(b[0]), "r"(b[1]));
}

__device__ __forceinline__ void mm_issue(
        const __nv_bfloat16* __restrict__ Ah, const __nv_bfloat16* __restrict__ Al,
        const __nv_bfloat16* __restrict__ Bh, const __nv_bfloat16* __restrict__ Bl,
        uint32_t sbase, int k0) {
    #pragma unroll
    for (int i = 0; i < 2; i++) {
        const int idx = threadIdx.x + i * 256;   // 0..511
        const int row = idx >> 2, seg = idx & 3;
        const size_t go = (size_t)row * D_MODEL + k0 + seg * 8;
        const uint32_t so = sbase + (uint32_t)(row * MM_SA + seg * 8) * 2;
        cp_async16(so + 0 * MM_MAT, Ah + go);
        cp_async16(so + 1 * MM_MAT, Al + go);
        cp_async16(so + 2 * MM_MAT, Bh + go);
        cp_async16(so + 3 * MM_MAT, Bl + go);
    }
}

__device__ __forceinline__ void mm_compute(uint32_t sbase, float acc[4][4][4],
                                           int wm, int wn, int lane) {
    #pragma unroll
    for (int ks = 0; ks < 2; ks++) {
        uint32_t ah[4][4], al[4][4], bh[4][2], bl[4][2];
        const int acol = ks * 16 + (lane >> 4) * 8;
        #pragma unroll
        for (int mi = 0; mi < 4; mi++) {
            const int row = wm * 64 + mi * 16 + (lane & 15);
            const uint32_t off = (uint32_t)(row * MM_SA + acol) * 2;
            ldsm_x4(ah[mi], sbase + 0 * MM_MAT + off);
            ldsm_x4(al[mi], sbase + 1 * MM_MAT + off);
        }
        const int bcol = ks * 16 + ((lane >> 3) & 1) * 8;
        #pragma unroll
        for (int ni = 0; ni < 4; ni++) {
            const int nrow = wn * 32 + ni * 8 + (lane & 7);
            const uint32_t off = (uint32_t)(nrow * MM_SA + bcol) * 2;
            ldsm_x2(bh[ni], sbase + 2 * MM_MAT + off);
            ldsm_x2(bl[ni], sbase + 3 * MM_MAT + off);
        }
        #pragma unroll
        for (int mi = 0; mi < 4; mi++)
            #pragma unroll
            for (int ni = 0; ni < 4; ni++) {
                mma16816(acc[mi][ni], ah[mi], bh[ni]);
                mma16816(acc[mi][ni], al[mi], bh[ni]);
                mma16816(acc[mi][ni], ah[mi], bl[ni]);
            }
    }
}

__device__ __forceinline__ void gemm_tile_mma(
        const __nv_bfloat16* __restrict__ Ah, const __nv_bfloat16* __restrict__ Al,
        const __nv_bfloat16* __restrict__ Bh, const __nv_bfloat16* __restrict__ Bl,
        char* smem, uint32_t sb, float acc[4][4][4]) {
    const int lane = threadIdx.x & 31;
    const int wid = threadIdx.x >> 5;
    const int wm = wid >> 2, wn = wid & 3;

    mm_issue(Ah, Al, Bh, Bl, sb, 0);
    CP_COMMIT();
    for (int c = 0; c < D_MODEL / 32; c++) {
        if (c + 1 < D_MODEL / 32)
            mm_issue(Ah, Al, Bh, Bl, sb + ((c + 1) & 1) * MM_STAGE, (c + 1) * 32);
        CP_COMMIT();
        CP_WAIT1();
        __syncthreads();
        mm_compute(sb + (c & 1) * MM_STAGE, acc, wm, wn, lane);
        __syncthreads();
    }
}

// ------------------------------- QKV GEMM -----------------------------------
__global__ __launch_bounds__(256, 1) void qkv_tc_kernel() {
    extern __shared__ __align__(1024) char smem[];
    const uint32_t sb = smem_u32(smem);
    const int z = blockIdx.z;
    const int head = blockIdx.x;
    const int row0 = blockIdx.y * 128;
    const int col0 = head * 128;

    const __nv_bfloat16* Ah = g_xh + (size_t)row0 * D_MODEL;
    const __nv_bfloat16* Al = g_xl + (size_t)row0 * D_MODEL;
    const __nv_bfloat16* Bh = g_wh + (size_t)z * W_ELEMS + (size_t)col0 * D_MODEL;
    const __nv_bfloat16* Bl = g_wl + (size_t)z * W_ELEMS + (size_t)col0 * D_MODEL;
    float* outp = (z == 0) ? g_q : (z == 1) ? g_k : g_v;

#if USE_TCGEN05
    uint32_t tmem = gemm_tile_tc(Ah, Al, Bh, Bl, smem, sb);
    const int lane = threadIdx.x & 31, wid = threadIdx.x >> 5;
    const int sub = wid & 3, half = wid >> 2;
    const int gr = row0 + sub * 32 + lane;
    const int b = gr >> 11, s = gr & 2047;
    float* dst = outp + ((size_t)((b * NHEADS + head) * S_LEN + s) << 7) + half * 64;
    uint32_t r[32];
    #pragma unroll
    for (int i = 0; i < 2; i++) {
        TCGEN05_LD_32X32B_X32(r, tmem + half * 64 + i * 32);
        TCGEN05_WAIT_LD();
        #pragma unroll
        for (int j = 0; j < 32; j += 4)
            *(float4*)(dst + i * 32 + j) = make_float4(
                __uint_as_float(r[j]), __uint_as_float(r[j + 1]),
                __uint_as_float(r[j + 2]), __uint_as_float(r[j + 3]));
    }
    TCGEN05_FENCE_BEFORE();
    __syncthreads();
    if (threadIdx.x == 0) MBARRIER_INVAL(sb + 8);
    if (wid == 0) TCGEN05_DEALLOC(tmem, 128);
#else
    float acc[4][4][4];
    #pragma unroll
    for (int mi = 0; mi < 4; mi++)
        #pragma unroll
        for (int ni = 0; ni < 4; ni++)
            #pragma unroll
            for (int k = 0; k < 4; k++) acc[mi][ni][k] = 0.f;

    gemm_tile_mma(Ah, Al, Bh, Bl, smem, sb, acc);

    const int lane = threadIdx.x & 31, wid = threadIdx.x >> 5;
    const int wm = wid >> 2, wn = wid & 3;
    #pragma unroll
    for (int mi = 0; mi < 4; mi++) {
        const int r0_ = row0 + wm * 64 + mi * 16 + (lane >> 2);
        #pragma unroll
        for (int rr = 0; rr < 2; rr++) {
            const int gr = r0_ + rr * 8;
            const int b = gr >> 11, s = gr & 2047;
            float* dst = outp + ((size_t)((b * NHEADS + head) * S_LEN + s) << 7);
            #pragma unroll
            for (int ni = 0; ni < 4; ni++) {
                const int col = wn * 32 + ni * 8 + (lane & 3) * 2;
                *(float2*)(dst + col) =
                    make_float2(acc[mi][ni][rr * 2 + 0], acc[mi][ni][rr * 2 + 1]);
            }
        }
    }
#endif
}

// ------------------------------- OUT GEMM -----------------------------------
__global__ __launch_bounds__(256, 1) void out_tc_kernel(float* __restrict__ C) {
    extern __shared__ __align__(1024) char smem[];
    const uint32_t sb = smem_u32(smem);
    const int row0 = blockIdx.y * 128;
    const int col0 = blockIdx.x * 128;

    const __nv_bfloat16* Ah = g_ah + (size_t)row0 * D_MODEL;
    const __nv_bfloat16* Al = g_al + (size_t)row0 * D_MODEL;
    const __nv_bfloat16* Bh = g_wh + 3 * W_ELEMS + (size_t)col0 * D_MODEL;
    const __nv_bfloat16* Bl = g_wl + 3 * W_ELEMS + (size_t)col0 * D_MODEL;

#if USE_TCGEN05
    uint32_t tmem = gemm_tile_tc(Ah, Al, Bh, Bl, smem, sb);
    const int lane = threadIdx.x & 31, wid = threadIdx.x >> 5;
    const int sub = wid & 3, half = wid >> 2;
    const int gr = row0 + sub * 32 + lane;
    float* dst = C + (size_t)gr * D_MODEL + col0 + half * 64;
    uint32_t r[32];
    #pragma unroll
    for (int i = 0; i < 2; i++) {
        TCGEN05_LD_32X32B_X32(r, tmem + half * 64 + i * 32);
        TCGEN05_WAIT_LD();
        #pragma unroll
        for (int j = 0; j < 32; j += 4)
            *(float4*)(dst + i * 32 + j) = make_float4(
                __uint_as_float(r[j]), __uint_as_float(r[j + 1]),
                __uint_as_float(r[j + 2]), __uint_as_float(r[j + 3]));
    }
    TCGEN05_FENCE_BEFORE();
    __syncthreads();
    if (threadIdx.x == 0) MBARRIER_INVAL(sb + 8);
    if (wid == 0) TCGEN05_DEALLOC(tmem, 128);
#else
    float acc[4][4][4];
    #pragma unroll
    for (int mi = 0; mi < 4; mi++)
        #pragma unroll
        for (int ni = 0; ni < 4; ni++)
            #pragma unroll
            for (int k = 0; k < 4; k++) acc[mi][ni][k] = 0.f;

    gemm_tile_mma(Ah, Al, Bh, Bl, smem, sb, acc);

    const int lane = threadIdx.x & 31, wid = threadIdx.x >> 5;
    const int wm = wid >> 2, wn = wid & 3;
    #pragma unroll
    for (int mi = 0; mi < 4; mi++) {
        const int r0_ = row0 + wm * 64 + mi * 16 + (lane >> 2);
        #pragma unroll
        for (int rr = 0; rr < 2; rr++) {
            float* dst = C + (size_t)(r0_ + rr * 8) * D_MODEL + col0;
            #pragma unroll
            for (int ni = 0; ni < 4; ni++) {
                const int col = wn * 32 + ni * 8 + (lane & 3) * 2;
                *(float2*)(dst + col) =
                    make_float2(acc[mi][ni][rr * 2 + 0], acc[mi][ni][rr * 2 + 1]);
            }
        }
    }
#endif
}

// ---------------------------- bf16 split kernels ----------------------------
__device__ __forceinline__ void split1(float v, __nv_bfloat16& h, __nv_bfloat16& l) {
    h = __float2bfloat16(v);
    l = __float2bfloat16(v - __bfloat162float(h));
}

__global__ __launch_bounds__(256) void split_x_kernel(const float* __restrict__ src) {
    size_t i = ((size_t)blockIdx.x * 256 + threadIdx.x) * 4;
    float4 v = *(const float4*)(src + i);
    __nv_bfloat16 h[4], l[4];
    split1(v.x, h[0], l[0]); split1(v.y, h[1], l[1]);
    split1(v.z, h[2], l[2]); split1(v.w, h[3], l[3]);
    *(uint2*)(g_xh + i) = *(uint2*)h;
    *(uint2*)(g_xl + i) = *(uint2*)l;
}

__global__ __launch_bounds__(256) void split_w_kernel(const float* __restrict__ src, int which) {
    size_t i = ((size_t)blockIdx.x * 256 + threadIdx.x) * 4;
    float4 v = *(const float4*)(src + i);
    __nv_bfloat16 h[4], l[4];
    split1(v.x, h[0], l[0]); split1(v.y, h[1], l[1]);
    split1(v.z, h[2], l[2]); split1(v.w, h[3], l[3]);
    *(uint2*)(g_wh + (size_t)which * W_ELEMS + i) = *(uint2*)h;
    *(uint2*)(g_wl + (size_t)which * W_ELEMS + i) = *(uint2*)l;
}

__global__ __launch_bounds__(256) void split_a_kernel() {
    size_t i = ((size_t)blockIdx.x * 256 + threadIdx.x) * 4;
    float4 v = *(const float4*)(g_attn + i);
    __nv_bfloat16 h[4], l[4];
    split1(v.x, h[0], l[0]); split1(v.y, h[1], l[1]);
    split1(v.z, h[2], l[2]); split1(v.w, h[3], l[3]);
    *(uint2*)(g_ah + i) = *(uint2*)h;
    *(uint2*)(g_al + i) = *(uint2*)l;
}

// ---------------------------- flash attention (fp32) ------------------------
#define TQ 64
#define TK 64
#define KSTR 68
#define PSTR 65
#define FLASH_SMEM_FLOATS (TQ*HDIM + HDIM*KSTR + TK*HDIM + TQ*PSTR + 3*TQ)
#define FLASH_SMEM_BYTES  (FLASH_SMEM_FLOATS * 4)

__global__ __launch_bounds__(256) void flash_kernel() {
    extern __shared__ __align__(16) float sm[];
    float* Qs   = sm;
    float* Ks   = Qs + TQ * HDIM;
    float* Vs   = Ks + HDIM * KSTR;
    float* Ps   = Vs + TK * HDIM;
    float* mrow = Ps + TQ * PSTR;
    float* lrow = mrow + TQ;
    float* rsc  = lrow + TQ;

    const int tid = threadIdx.x;
    const int tx = tid & 15, ty = tid >> 4;
    const int q0 = blockIdx.x * TQ;
    const int bh = blockIdx.y;
    const float* Qp = g_q + (size_t)bh * S_LEN * HDIM;
    const float* Kp = g_k + (size_t)bh * S_LEN * HDIM;
    const float* Vp = g_v + (size_t)bh * S_LEN * HDIM;
    const float NEG_INF = __int_as_float(0xff800000);

    for (int p = tid; p < TQ * HDIM / 4; p += 256) {
        const int r = p >> 5, c = (p & 31) << 2;
        *(float4*)(Qs + r * HDIM + c) = *(const float4*)(Qp + (size_t)(q0 + r) * HDIM + c);
    }
    if (tid < TQ) { mrow[tid] = NEG_INF; lrow[tid] = 0.f; }

    float acc[4][8];
    #pragma unroll
    for (int r = 0; r < 4; r++)
        #pragma unroll
        for (int j = 0; j < 8; j++) acc[r][j] = 0.f;

    const int ntiles = blockIdx.x + 1;
    for (int t = 0; t < ntiles; t++) {
        const int k0 = t * TK;
        __syncthreads();
        for (int p = tid; p < TK * HDIM / 4; p += 256) {
            const int r = p >> 5, c = (p & 31) << 2;
            float4 kv = *(const float4*)(Kp + (size_t)(k0 + r) * HDIM + c);
            Ks[(c + 0) * KSTR + r] = kv.x;
            Ks[(c + 1) * KSTR + r] = kv.y;
            Ks[(c + 2) * KSTR + r] = kv.z;
            Ks[(c + 3) * KSTR + r] = kv.w;
            *(float4*)(Vs + r * HDIM + c) = *(const float4*)(Vp + (size_t)(k0 + r) * HDIM + c);
        }
        __syncthreads();

        float s_[4][4];
        #pragma unroll
        for (int r = 0; r < 4; r++)
            #pragma unroll
            for (int c = 0; c < 4; c++) s_[r][c] = 0.f;

        #pragma unroll 2
        for (int d = 0; d < HDIM; d += 4) {
            float kv[4][4];
            #pragma unroll
            for (int dd = 0; dd < 4; dd++) {
                float4 kf = *(const float4*)(Ks + (d + dd) * KSTR + tx * 4);
                kv[dd][0] = kf.x; kv[dd][1] = kf.y; kv[dd][2] = kf.z; kv[dd][3] = kf.w;
            }
            #pragma unroll
            for (int r = 0; r < 4; r++) {
                float4 qf = *(const float4*)(Qs + (ty * 4 + r) * HDIM + d);
                float qv[4] = {qf.x, qf.y, qf.z, qf.w};
                #pragma unroll
                for (int dd = 0; dd < 4; dd++)
                    #pragma unroll
                    for (int c = 0; c < 4; c++)
                        s_[r][c] = fmaf(qv[dd], kv[dd][c], s_[r][c]);
            }
        }

        const float qsc = 0.08838834764831845f;
        if (t == ntiles - 1) {
            #pragma unroll
            for (int r = 0; r < 4; r++)
                #pragma unroll
                for (int c = 0; c < 4; c++) {
                    const int gq_ = q0 + ty * 4 + r;
                    const int gk_ = k0 + tx * 4 + c;
                    Ps[(ty * 4 + r) * PSTR + tx * 4 + c] =
                        (gk_ > gq_) ? NEG_INF : s_[r][c] * qsc;
                }
        } else {
            #pragma unroll
            for (int r = 0; r < 4; r++)
                #pragma unroll
                for (int c = 0; c < 4; c++)
                    Ps[(ty * 4 + r) * PSTR + tx * 4 + c] = s_[r][c] * qsc;
        }
        __syncthreads();

        if (tid < TQ) {
            const float mo = mrow[tid];
            float mx = mo;
            #pragma unroll 4
            for (int k = 0; k < TK; k++) mx = fmaxf(mx, Ps[tid * PSTR + k]);
            const float scl = __expf(mo - mx);
            float l = lrow[tid] * scl;
            #pragma unroll 4
            for (int k = 0; k < TK; k++) {
                const float e = __expf(Ps[tid * PSTR + k] - mx);
                Ps[tid * PSTR + k] = e;
                l += e;
            }
            mrow[tid] = mx; lrow[tid] = l; rsc[tid] = scl;
        }
        __syncthreads();

        float rs[4];
        #pragma unroll
        for (int r = 0; r < 4; r++) rs[r] = rsc[ty * 4 + r];
        #pragma unroll
        for (int r = 0; r < 4; r++)
            #pragma unroll
            for (int j = 0; j < 8; j++) acc[r][j] *= rs[r];

        #pragma unroll 2
        for (int k = 0; k < TK; k++) {
            float pv[4];
            #pragma unroll
            for (int r = 0; r < 4; r++) pv[r] = Ps[(ty * 4 + r) * PSTR + k];
            const float4 v0 = *(const float4*)(Vs + k * HDIM + tx * 4);
            const float4 v1 = *(const float4*)(Vs + k * HDIM + 64 + tx * 4);
            #pragma unroll
            for (int r = 0; r < 4; r++) {
                acc[r][0] = fmaf(pv[r], v0.x, acc[r][0]);
                acc[r][1] = fmaf(pv[r], v0.y, acc[r][1]);
                acc[r][2] = fmaf(pv[r], v0.z, acc[r][2]);
                acc[r][3] = fmaf(pv[r], v0.w, acc[r][3]);
                acc[r][4] = fmaf(pv[r], v1.x, acc[r][4]);
                acc[r][5] = fmaf(pv[r], v1.y, acc[r][5]);
                acc[r][6] = fmaf(pv[r], v1.z, acc[r][6]);
                acc[r][7] = fmaf(pv[r], v1.w, acc[r][7]);
            }
        }
    }

    const int b = bh >> 4, h = bh & 15;
    #pragma unroll
    for (int r = 0; r < 4; r++) {
        const int s = q0 + ty * 4 + r;
        const float inv = 1.0f / lrow[ty * 4 + r];
        float* dst = g_attn + (size_t)(b * S_LEN + s) * D_MODEL + h * HDIM;
        *(float4*)(dst + tx * 4) =
            make_float4(acc[r][0] * inv, acc[r][1] * inv, acc[r][2] * inv, acc[r][3] * inv);
        *(float4*)(dst + 64 + tx * 4) =
            make_float4(acc[r][4] * inv, acc[r][5] * inv, acc[r][6] * inv, acc[r][7] * inv);
    }
}

// ---------------------------------------------------------------------------
extern "C" void kernel_launch(void* const* d_in, const int* in_sizes, int n_in,
                              void* d_out, int out_size) {
    const float* x  = (const float*)d_in[0];
    const float* wq = (const float*)d_in[1];
    const float* wk = (const float*)d_in[2];
    const float* wv = (const float*)d_in[3];
    const float* wo = (const float*)d_in[4];
    float* out = (float*)d_out;

    cudaFuncSetAttribute(flash_kernel, cudaFuncAttributeMaxDynamicSharedMemorySize,
                         FLASH_SMEM_BYTES);
    cudaFuncSetAttribute(qkv_tc_kernel, cudaFuncAttributeMaxDynamicSharedMemorySize,
                         GEMM_SMEM_BYTES);
    cudaFuncSetAttribute(out_tc_kernel, cudaFuncAttributeMaxDynamicSharedMemorySize,
                         GEMM_SMEM_BYTES);

    split_x_kernel<<<(unsigned)(X_ELEMS / 4 / 256), 256>>>(x);
    split_w_kernel<<<(unsigned)(W_ELEMS / 4 / 256), 256>>>(wq, 0);
    split_w_kernel<<<(unsigned)(W_ELEMS / 4 / 256), 256>>>(wk, 1);
    split_w_kernel<<<(unsigned)(W_ELEMS / 4 / 256), 256>>>(wv, 2);
    split_w_kernel<<<(unsigned)(W_ELEMS / 4 / 256), 256>>>(wo, 3);

    qkv_tc_kernel<<<dim3(D_MODEL / 128, NROWS / 128, 3), 256, GEMM_SMEM_BYTES>>>();
    flash_kernel<<<dim3(S_LEN / TQ, BATCH * NHEADS), 256, FLASH_SMEM_BYTES>>>();
    split_a_kernel<<<(unsigned)(X_ELEMS / 4 / 256), 256>>>();
    out_tc_kernel<<<dim3(D_MODEL / 128, NROWS / 128), 256, GEMM_SMEM_BYTES>>>(out);
}

// round 9
// speedup vs baseline: 2.4960x; 1.1878x over previous
#include <cuda_runtime.h>
#include <cuda_bf16.h>
#include <cstdint>

// Problem constants
#define D_MODEL 2048
#define S_LEN   2048
#define BATCH   2
#define NHEADS  16
#define HDIM    128
#define NROWS   (BATCH * S_LEN)          // 4096
#define X_ELEMS ((size_t)NROWS * D_MODEL)        // 8388608
#define W_ELEMS ((size_t)D_MODEL * D_MODEL)      // 4194304
#define QKV_ELEMS ((size_t)BATCH * NHEADS * S_LEN * HDIM)   // 8388608

// ------------------------- scratch (device globals) -------------------------
__device__ __nv_bfloat16 g_xh[X_ELEMS], g_xl[X_ELEMS];
__device__ __nv_bfloat16 g_wh[4 * W_ELEMS], g_wl[4 * W_ELEMS]; // q,k,v,o
__device__ __nv_bfloat16 g_qh[QKV_ELEMS], g_ql[QKV_ELEMS];     // [bh][s][dh]
__device__ __nv_bfloat16 g_kh[QKV_ELEMS], g_kl[QKV_ELEMS];
__device__ __nv_bfloat16 g_vh[QKV_ELEMS], g_vl[QKV_ELEMS];
__device__ __nv_bfloat16 g_ah[X_ELEMS], g_al[X_ELEMS];         // [b*s][h*128+dh]

// ------------------------- common helpers ----------------------------------
__device__ __forceinline__ uint32_t smem_u32(const void* p) {
    uint32_t a;
    asm("{ .reg .u64 t; cvta.to.shared.u64 t, %1; cvt.u32.u64 %0, t; }"
        : "=r"(a) : "l"(p));
    return a;
}

__device__ __forceinline__ void cp_async16(uint32_t s, const void* g) {
    asm volatile("cp.async.ca.shared.global [%0], [%1], 16;"
                 :: "r"(s), "l"(g) : "memory");
}
#define CP_COMMIT() asm volatile("cp.async.commit_group;" ::: "memory")
#define CP_WAIT1()  asm volatile("cp.async.wait_group 1;" ::: "memory")

__device__ __forceinline__ void ldsm_x4(uint32_t* r, uint32_t addr) {
    asm volatile("ldmatrix.sync.aligned.m8n8.x4.shared.b16 {%0,%1,%2,%3}, [%4];"
                 : "=r"(r[0]), "=r"(r[1]), "=r"(r[2]), "=r"(r[3]) : "r"(addr));
}
__device__ __forceinline__ void ldsm_x2(uint32_t* r, uint32_t addr) {
    asm volatile("ldmatrix.sync.aligned.m8n8.x2.shared.b16 {%0,%1}, [%2];"
                 : "=r"(r[0]), "=r"(r[1]) : "r"(addr));
}
__device__ __forceinline__ void mma16816(float* d, const uint32_t* a, const uint32_t* b) {
    asm volatile("mma.sync.aligned.m16n8k16.row.col.f32.bf16.bf16.f32 "
        "{%0,%1,%2,%3}, {%4,%5,%6,%7}, {%8,%9}, {%0,%1,%2,%3};"
        : "+f"(d[0]), "+f"(d[1]), "+f"(d[2]), "+f"(d[3])
        : "r"(a[0]), "r"(a[1]), "r"(a[2]), "r"(a[3]), "r"(b[0]), "r"(b[1]));
}

__device__ __forceinline__ void split1(float v, __nv_bfloat16& h, __nv_bfloat16& l) {
    h = __float2bfloat16(v);
    l = __float2bfloat16(v - __bfloat162float(h));
}
__device__ __forceinline__ uint32_t pack_bf16(__nv_bfloat16 a, __nv_bfloat16 b) {
    union { __nv_bfloat162 v; uint32_t u; } u;
    u.v = __nv_bfloat162(a, b);
    return u.u;
}

// ===================== mma.sync GEMM (proven, unchanged core) ================
// 128x128 CTA tile, 256 threads = 8 warps in 2(m) x 4(n); warp tile 64x32.
// D += Ah*Bh + Al*Bh + Ah*Bl. cp.async double-buffered K=32.
#define MM_SA     40
#define MM_MAT    10240
#define MM_STAGE  40960
#define GEMM_SMEM_BYTES 81920

__device__ __forceinline__ void mm_issue(
        const __nv_bfloat16* __restrict__ Ah, const __nv_bfloat16* __restrict__ Al,
        const __nv_bfloat16* __restrict__ Bh, const __nv_bfloat16* __restrict__ Bl,
        uint32_t sbase, int k0) {
    #pragma unroll
    for (int i = 0; i < 2; i++) {
        const int idx = threadIdx.x + i * 256;
        const int row = idx >> 2, seg = idx & 3;
        const size_t go = (size_t)row * D_MODEL + k0 + seg * 8;
        const uint32_t so = sbase + (uint32_t)(row * MM_SA + seg * 8) * 2;
        cp_async16(so + 0 * MM_MAT, Ah + go);
        cp_async16(so + 1 * MM_MAT, Al + go);
        cp_async16(so + 2 * MM_MAT, Bh + go);
        cp_async16(so + 3 * MM_MAT, Bl + go);
    }
}

__device__ __forceinline__ void mm_compute(uint32_t sbase, float acc[4][4][4],
                                           int wm, int wn, int lane) {
    #pragma unroll
    for (int ks = 0; ks < 2; ks++) {
        uint32_t ah[4][4], al[4][4], bh[4][2], bl[4][2];
        const int acol = ks * 16 + (lane >> 4) * 8;
        #pragma unroll
        for (int mi = 0; mi < 4; mi++) {
            const int row = wm * 64 + mi * 16 + (lane & 15);
            const uint32_t off = (uint32_t)(row * MM_SA + acol) * 2;
            ldsm_x4(ah[mi], sbase + 0 * MM_MAT + off);
            ldsm_x4(al[mi], sbase + 1 * MM_MAT + off);
        }
        const int bcol = ks * 16 + ((lane >> 3) & 1) * 8;
        #pragma unroll
        for (int ni = 0; ni < 4; ni++) {
            const int nrow = wn * 32 + ni * 8 + (lane & 7);
            const uint32_t off = (uint32_t)(nrow * MM_SA + bcol) * 2;
            ldsm_x2(bh[ni], sbase + 2 * MM_MAT + off);
            ldsm_x2(bl[ni], sbase + 3 * MM_MAT + off);
        }
        #pragma unroll
        for (int mi = 0; mi < 4; mi++)
            #pragma unroll
            for (int ni = 0; ni < 4; ni++) {
                mma16816(acc[mi][ni], ah[mi], bh[ni]);
                mma16816(acc[mi][ni], al[mi], bh[ni]);
                mma16816(acc[mi][ni], ah[mi], bl[ni]);
            }
    }
}

__device__ __forceinline__ void gemm_tile_mma(
        const __nv_bfloat16* __restrict__ Ah, const __nv_bfloat16* __restrict__ Al,
        const __nv_bfloat16* __restrict__ Bh, const __nv_bfloat16* __restrict__ Bl,
        uint32_t sb, float acc[4][4][4]) {
    const int lane = threadIdx.x & 31;
    const int wid = threadIdx.x >> 5;
    const int wm = wid >> 2, wn = wid & 3;

    mm_issue(Ah, Al, Bh, Bl, sb, 0);
    CP_COMMIT();
    for (int c = 0; c < D_MODEL / 32; c++) {
        if (c + 1 < D_MODEL / 32)
            mm_issue(Ah, Al, Bh, Bl, sb + ((c + 1) & 1) * MM_STAGE, (c + 1) * 32);
        CP_COMMIT();
        CP_WAIT1();
        __syncthreads();
        mm_compute(sb + (c & 1) * MM_STAGE, acc, wm, wn, lane);
        __syncthreads();
    }
}

// ------------------------------- QKV GEMM -----------------------------------
// Epilogue writes bf16 hi/lo directly into g_{q,k,v}{h,l} [bh][s][dh].
__global__ __launch_bounds__(256, 1) void qkv_tc_kernel() {
    extern __shared__ __align__(1024) char smem[];
    const uint32_t sb = smem_u32(smem);
    const int z = blockIdx.z;
    const int head = blockIdx.x;
    const int row0 = blockIdx.y * 128;

    const __nv_bfloat16* Ah = g_xh + (size_t)row0 * D_MODEL;
    const __nv_bfloat16* Al = g_xl + (size_t)row0 * D_MODEL;
    const __nv_bfloat16* Bh = g_wh + (size_t)z * W_ELEMS + (size_t)head * 128 * D_MODEL;
    const __nv_bfloat16* Bl = g_wl + (size_t)z * W_ELEMS + (size_t)head * 128 * D_MODEL;
    __nv_bfloat16* dsth = (z == 0) ? g_qh : (z == 1) ? g_kh : g_vh;
    __nv_bfloat16* dstl = (z == 0) ? g_ql : (z == 1) ? g_kl : g_vl;

    float acc[4][4][4];
    #pragma unroll
    for (int mi = 0; mi < 4; mi++)
        #pragma unroll
        for (int ni = 0; ni < 4; ni++)
            #pragma unroll
            for (int k = 0; k < 4; k++) acc[mi][ni][k] = 0.f;

    gemm_tile_mma(Ah, Al, Bh, Bl, sb, acc);

    const int lane = threadIdx.x & 31, wid = threadIdx.x >> 5;
    const int wm = wid >> 2, wn = wid & 3;
    #pragma unroll
    for (int mi = 0; mi < 4; mi++) {
        const int r0_ = row0 + wm * 64 + mi * 16 + (lane >> 2);
        #pragma unroll
        for (int rr = 0; rr < 2; rr++) {
            const int gr = r0_ + rr * 8;
            const int b = gr >> 11, s = gr & 2047;
            const size_t base = ((size_t)((b * NHEADS + head) * S_LEN + s)) << 7;
            #pragma unroll
            for (int ni = 0; ni < 4; ni++) {
                const int col = wn * 32 + ni * 8 + (lane & 3) * 2;
                __nv_bfloat16 h0, l0, h1, l1;
                split1(acc[mi][ni][rr * 2 + 0], h0, l0);
                split1(acc[mi][ni][rr * 2 + 1], h1, l1);
                *(uint32_t*)(dsth + base + col) = pack_bf16(h0, h1);
                *(uint32_t*)(dstl + base + col) = pack_bf16(l0, l1);
            }
        }
    }
}

// ------------------------------- OUT GEMM -----------------------------------
__global__ __launch_bounds__(256, 1) void out_tc_kernel(float* __restrict__ C) {
    extern __shared__ __align__(1024) char smem[];
    const uint32_t sb = smem_u32(smem);
    const int row0 = blockIdx.y * 128;
    const int col0 = blockIdx.x * 128;

    const __nv_bfloat16* Ah = g_ah + (size_t)row0 * D_MODEL;
    const __nv_bfloat16* Al = g_al + (size_t)row0 * D_MODEL;
    const __nv_bfloat16* Bh = g_wh + 3 * W_ELEMS + (size_t)col0 * D_MODEL;
    const __nv_bfloat16* Bl = g_wl + 3 * W_ELEMS + (size_t)col0 * D_MODEL;

    float acc[4][4][4];
    #pragma unroll
    for (int mi = 0; mi < 4; mi++)
        #pragma unroll
        for (int ni = 0; ni < 4; ni++)
            #pragma unroll
            for (int k = 0; k < 4; k++) acc[mi][ni][k] = 0.f;

    gemm_tile_mma(Ah, Al, Bh, Bl, sb, acc);

    const int lane = threadIdx.x & 31, wid = threadIdx.x >> 5;
    const int wm = wid >> 2, wn = wid & 3;
    #pragma unroll
    for (int mi = 0; mi < 4; mi++) {
        const int r0_ = row0 + wm * 64 + mi * 16 + (lane >> 2);
        #pragma unroll
        for (int rr = 0; rr < 2; rr++) {
            float* dst = C + (size_t)(r0_ + rr * 8) * D_MODEL + col0;
            #pragma unroll
            for (int ni = 0; ni < 4; ni++) {
                const int col = wn * 32 + ni * 8 + (lane & 3) * 2;
                *(float2*)(dst + col) =
                    make_float2(acc[mi][ni][rr * 2 + 0], acc[mi][ni][rr * 2 + 1]);
            }
        }
    }
}

// ---------------------------- bf16 split kernels ----------------------------
__global__ __launch_bounds__(256) void split_x_kernel(const float* __restrict__ src) {
    size_t i = ((size_t)blockIdx.x * 256 + threadIdx.x) * 4;
    float4 v = *(const float4*)(src + i);
    __nv_bfloat16 h[4], l[4];
    split1(v.x, h[0], l[0]); split1(v.y, h[1], l[1]);
    split1(v.z, h[2], l[2]); split1(v.w, h[3], l[3]);
    *(uint2*)(g_xh + i) = *(uint2*)h;
    *(uint2*)(g_xl + i) = *(uint2*)l;
}

__global__ __launch_bounds__(256) void split_w_kernel(const float* __restrict__ src, int which) {
    size_t i = ((size_t)blockIdx.x * 256 + threadIdx.x) * 4;
    float4 v = *(const float4*)(src + i);
    __nv_bfloat16 h[4], l[4];
    split1(v.x, h[0], l[0]); split1(v.y, h[1], l[1]);
    split1(v.z, h[2], l[2]); split1(v.w, h[3], l[3]);
    *(uint2*)(g_wh + (size_t)which * W_ELEMS + i) = *(uint2*)h;
    *(uint2*)(g_wl + (size_t)which * W_ELEMS + i) = *(uint2*)l;
}

// ======================= flash attention (mma.sync) =========================
// Block: 128 q-rows x one (b,h); 8 warps, each warp owns 16 q-rows.
// K-tiles of 64. Q[128x128], K[64x128] in smem row-major ([m|n][k], proven
// GEMM fragment paths); V stored TRANSPOSED in smem ([dh][s] = [n][k], same
// proven B path). P fragments built from S accumulators (FA2 identity).
#define FQSTR 136     // Q/K smem row stride (bf16 elems); 272B = 4 mod 32 words
#define FVSTR 72      // Vt smem row stride; 144B = 4 mod 32 words
#define FOFF_QH 0
#define FOFF_QL (FOFF_QH + 128 * FQSTR * 2)      // 34816
#define FOFF_KH (FOFF_QL + 128 * FQSTR * 2)      // 69632
#define FOFF_KL (FOFF_KH + 64 * FQSTR * 2)       // 87040
#define FOFF_VH (FOFF_KL + 64 * FQSTR * 2)       // 104448
#define FOFF_VL (FOFF_VH + 128 * FVSTR * 2)      // 122880
#define FLASH_SMEM_BYTES (FOFF_VL + 128 * FVSTR * 2)   // 141312

__global__ __launch_bounds__(256, 1) void flash_mma_kernel() {
    extern __shared__ __align__(1024) char smem[];
    const uint32_t sb = smem_u32(smem);
    const int tid = threadIdx.x;
    const int lane = tid & 31;
    const int w = tid >> 5;
    const int qblk = gridDim.x - 1 - blockIdx.x;   // heavy blocks first
    const int q0 = qblk * 128;
    const int bh = blockIdx.y;

    const __nv_bfloat16* Qhp = g_qh + ((size_t)bh * S_LEN + q0) * HDIM;
    const __nv_bfloat16* Qlp = g_ql + ((size_t)bh * S_LEN + q0) * HDIM;
    const __nv_bfloat16* Khp = g_kh + (size_t)bh * S_LEN * HDIM;
    const __nv_bfloat16* Klp = g_kl + (size_t)bh * S_LEN * HDIM;
    const __nv_bfloat16* Vhp = g_vh + (size_t)bh * S_LEN * HDIM;
    const __nv_bfloat16* Vlp = g_vl + (size_t)bh * S_LEN * HDIM;

    // Load Q tile (128x128) hi/lo into padded smem
    #pragma unroll
    for (int i = 0; i < 8; i++) {
        const int idx = tid + i * 256;              // 0..2047
        const int r = idx >> 4, c8 = (idx & 15) * 8;
        const uint32_t so = (uint32_t)(r * FQSTR + c8) * 2;
        *(uint4*)(smem + FOFF_QH + so) = *(const uint4*)(Qhp + (size_t)r * HDIM + c8);
        *(uint4*)(smem + FOFF_QL + so) = *(const uint4*)(Qlp + (size_t)r * HDIM + c8);
    }

    const float NEG_INF = __int_as_float(0xff800000);
    const float qsc = 0.08838834764831845f;         // 1/sqrt(128)
    float m0 = NEG_INF, m1 = NEG_INF, l0 = 0.f, l1 = 0.f;
    float O[16][4];
    #pragma unroll
    for (int j = 0; j < 16; j++)
        #pragma unroll
        for (int k = 0; k < 4; k++) O[j][k] = 0.f;

    const int ntiles = 2 * (qblk + 1);
    for (int t = 0; t < ntiles; t++) {
        const int k0 = t * 64;
        __syncthreads();                            // prior compute done
        // K tile (64x128) hi/lo, coalesced
        #pragma unroll
        for (int i = 0; i < 4; i++) {
            const int idx = tid + i * 256;          // 0..1023
            const int r = idx >> 4, c8 = (idx & 15) * 8;
            const uint32_t so = (uint32_t)(r * FQSTR + c8) * 2;
            *(uint4*)(smem + FOFF_KH + so) = *(const uint4*)(Khp + (size_t)(k0 + r) * HDIM + c8);
            *(uint4*)(smem + FOFF_KL + so) = *(const uint4*)(Klp + (size_t)(k0 + r) * HDIM + c8);
        }
        // V tile (64x128) hi/lo, transposed into [dh][s]
        #pragma unroll
        for (int i = 0; i < 4; i++) {
            const int idx = tid + i * 256;
            const int r = idx & 63, c8 = (idx >> 6) * 8;
            uint4 vh = *(const uint4*)(Vhp + (size_t)(k0 + r) * HDIM + c8);
            uint4 vl = *(const uint4*)(Vlp + (size_t)(k0 + r) * HDIM + c8);
            const __nv_bfloat16* eh = (const __nv_bfloat16*)&vh;
            const __nv_bfloat16* el = (const __nv_bfloat16*)&vl;
            #pragma unroll
            for (int e = 0; e < 8; e++) {
                const uint32_t so = (uint32_t)((c8 + e) * FVSTR + r) * 2;
                *(__nv_bfloat16*)(smem + FOFF_VH + so) = eh[e];
                *(__nv_bfloat16*)(smem + FOFF_VL + so) = el[e];
            }
        }
        __syncthreads();

        // ---- S = Q @ K^T (warp: 16 rows x 64 cols) ----
        float S[8][4];
        #pragma unroll
        for (int j = 0; j < 8; j++)
            #pragma unroll
            for (int k = 0; k < 4; k++) S[j][k] = 0.f;

        #pragma unroll
        for (int kt = 0; kt < 8; kt++) {
            uint32_t qa_h[4], qa_l[4];
            const int arow = w * 16 + (lane & 15);
            const int acol = kt * 16 + (lane >> 4) * 8;
            const uint32_t aoff = (uint32_t)(arow * FQSTR + acol) * 2;
            ldsm_x4(qa_h, sb + FOFF_QH + aoff);
            ldsm_x4(qa_l, sb + FOFF_QL + aoff);
            #pragma unroll
            for (int j = 0; j < 8; j++) {
                uint32_t kb_h[2], kb_l[2];
                const int nrow = j * 8 + (lane & 7);
                const int bcol = kt * 16 + ((lane >> 3) & 1) * 8;
                const uint32_t boff = (uint32_t)(nrow * FQSTR + bcol) * 2;
                ldsm_x2(kb_h, sb + FOFF_KH + boff);
                ldsm_x2(kb_l, sb + FOFF_KL + boff);
                mma16816(S[j], qa_h, kb_h);
                mma16816(S[j], qa_l, kb_h);
                mma16816(S[j], qa_h, kb_l);
            }
        }

        // scale + causal mask (only the last two tiles touch the diagonal)
        const int row0g = q0 + w * 16 + (lane >> 2);
        const int row1g = row0g + 8;
        if (k0 + 63 > q0) {
            #pragma unroll
            for (int j = 0; j < 8; j++) {
                const int colg = k0 + j * 8 + (lane & 3) * 2;
                S[j][0] = (colg     > row0g) ? NEG_INF : S[j][0] * qsc;
                S[j][1] = (colg + 1 > row0g) ? NEG_INF : S[j][1] * qsc;
                S[j][2] = (colg     > row1g) ? NEG_INF : S[j][2] * qsc;
                S[j][3] = (colg + 1 > row1g) ? NEG_INF : S[j][3] * qsc;
            }
        } else {
            #pragma unroll
            for (int j = 0; j < 8; j++) {
                S[j][0] *= qsc; S[j][1] *= qsc; S[j][2] *= qsc; S[j][3] *= qsc;
            }
        }

        // ---- online softmax (rows r0 = lane>>2, r1 = r0+8) ----
        float mx0 = m0, mx1 = m1;
        #pragma unroll
        for (int j = 0; j < 8; j++) {
            mx0 = fmaxf(mx0, fmaxf(S[j][0], S[j][1]));
            mx1 = fmaxf(mx1, fmaxf(S[j][2], S[j][3]));
        }
        mx0 = fmaxf(mx0, __shfl_xor_sync(0xffffffff, mx0, 1));
        mx0 = fmaxf(mx0, __shfl_xor_sync(0xffffffff, mx0, 2));
        mx1 = fmaxf(mx1, __shfl_xor_sync(0xffffffff, mx1, 1));
        mx1 = fmaxf(mx1, __shfl_xor_sync(0xffffffff, mx1, 2));

        const float sc0 = __expf(m0 - mx0);   // 0 when m0 == -inf
        const float sc1 = __expf(m1 - mx1);
        m0 = mx0; m1 = mx1;

        float rs0 = 0.f, rs1 = 0.f;
        #pragma unroll
        for (int j = 0; j < 8; j++) {
            S[j][0] = __expf(S[j][0] - mx0);
            S[j][1] = __expf(S[j][1] - mx0);
            S[j][2] = __expf(S[j][2] - mx1);
            S[j][3] = __expf(S[j][3] - mx1);
            rs0 += S[j][0] + S[j][1];
            rs1 += S[j][2] + S[j][3];
        }
        rs0 += __shfl_xor_sync(0xffffffff, rs0, 1);
        rs0 += __shfl_xor_sync(0xffffffff, rs0, 2);
        rs1 += __shfl_xor_sync(0xffffffff, rs1, 1);
        rs1 += __shfl_xor_sync(0xffffffff, rs1, 2);
        l0 = l0 * sc0 + rs0;
        l1 = l1 * sc1 + rs1;

        #pragma unroll
        for (int j = 0; j < 16; j++) {
            O[j][0] *= sc0; O[j][1] *= sc0; O[j][2] *= sc1; O[j][3] *= sc1;
        }

        // ---- P fragments (hi/lo) from S accumulators ----
        uint32_t pa_h[4][4], pa_l[4][4];
        #pragma unroll
        for (int pt = 0; pt < 4; pt++) {
            #pragma unroll
            for (int q = 0; q < 4; q++) {
                const int jj = pt * 2 + (q >> 1);       // a0,a1 -> tile 2pt; a2,a3 -> 2pt+1
                const int e0 = (q & 1) * 2;             // a0,a2 -> c0,c1; a1,a3 -> c2,c3
                __nv_bfloat16 h0, L0, h1, L1;
                split1(S[jj][e0 + 0], h0, L0);
                split1(S[jj][e0 + 1], h1, L1);
                pa_h[pt][q] = pack_bf16(h0, h1);
                pa_l[pt][q] = pack_bf16(L0, L1);
            }
        }

        // ---- O += P @ V (warp: 16 rows x 128 cols) ----
        #pragma unroll
        for (int pt = 0; pt < 4; pt++) {
            #pragma unroll
            for (int j = 0; j < 16; j++) {
                uint32_t vb_h[2], vb_l[2];
                const int nrow = j * 8 + (lane & 7);
                const int bcol = pt * 16 + ((lane >> 3) & 1) * 8;
                const uint32_t boff = (uint32_t)(nrow * FVSTR + bcol) * 2;
                ldsm_x2(vb_h, sb + FOFF_VH + boff);
                ldsm_x2(vb_l, sb + FOFF_VL + boff);
                mma16816(O[j], pa_h[pt], vb_h);
                mma16816(O[j], pa_l[pt], vb_h);
                mma16816(O[j], pa_h[pt], vb_l);
            }
        }
    }

    // ---- epilogue: normalize, write bf16 hi/lo into g_ah/g_al ----
    const float inv0 = 1.0f / l0;
    const float inv1 = 1.0f / l1;
    const int b = bh >> 4, h = bh & 15;
    const int s0 = q0 + w * 16 + (lane >> 2);
    const size_t base0 = (size_t)(b * S_LEN + s0) * D_MODEL + h * HDIM;
    const size_t base1 = (size_t)(b * S_LEN + s0 + 8) * D_MODEL + h * HDIM;
    #pragma unroll
    for (int j = 0; j < 16; j++) {
        const int col = j * 8 + (lane & 3) * 2;
        __nv_bfloat16 h0, L0, h1, L1;
        split1(O[j][0] * inv0, h0, L0);
        split1(O[j][1] * inv0, h1, L1);
        *(uint32_t*)(g_ah + base0 + col) = pack_bf16(h0, h1);
        *(uint32_t*)(g_al + base0 + col) = pack_bf16(L0, L1);
        split1(O[j][2] * inv1, h0, L0);
        split1(O[j][3] * inv1, h1, L1);
        *(uint32_t*)(g_ah + base1 + col) = pack_bf16(h0, h1);
        *(uint32_t*)(g_al + base1 + col) = pack_bf16(L0, L1);
    }
}

// ---------------------------------------------------------------------------
extern "C" void kernel_launch(void* const* d_in, const int* in_sizes, int n_in,
                              void* d_out, int out_size) {
    const float* x  = (const float*)d_in[0];
    const float* wq = (const float*)d_in[1];
    const float* wk = (const float*)d_in[2];
    const float* wv = (const float*)d_in[3];
    const float* wo = (const float*)d_in[4];
    float* out = (float*)d_out;

    cudaFuncSetAttribute(qkv_tc_kernel, cudaFuncAttributeMaxDynamicSharedMemorySize,
                         GEMM_SMEM_BYTES);
    cudaFuncSetAttribute(out_tc_kernel, cudaFuncAttributeMaxDynamicSharedMemorySize,
                         GEMM_SMEM_BYTES);
    cudaFuncSetAttribute(flash_mma_kernel, cudaFuncAttributeMaxDynamicSharedMemorySize,
                         FLASH_SMEM_BYTES);

    split_x_kernel<<<(unsigned)(X_ELEMS / 4 / 256), 256>>>(x);
    split_w_kernel<<<(unsigned)(W_ELEMS / 4 / 256), 256>>>(wq, 0);
    split_w_kernel<<<(unsigned)(W_ELEMS / 4 / 256), 256>>>(wk, 1);
    split_w_kernel<<<(unsigned)(W_ELEMS / 4 / 256), 256>>>(wv, 2);
    split_w_kernel<<<(unsigned)(W_ELEMS / 4 / 256), 256>>>(wo, 3);

    qkv_tc_kernel<<<dim3(D_MODEL / 128, NROWS / 128, 3), 256, GEMM_SMEM_BYTES>>>();
    flash_mma_kernel<<<dim3(S_LEN / 128, BATCH * NHEADS), 256, FLASH_SMEM_BYTES>>>();
    out_tc_kernel<<<dim3(D_MODEL / 128, NROWS / 128), 256, GEMM_SMEM_BYTES>>>(out);
}

// round 13
// speedup vs baseline: 2.7963x; 1.1203x over previous
#include <cuda_runtime.h>
#include <cuda_bf16.h>
#include <cstdint>

// Problem constants
#define D_MODEL 2048
#define S_LEN   2048
#define BATCH   2
#define NHEADS  16
#define HDIM    128
#define NROWS   (BATCH * S_LEN)          // 4096
#define X_ELEMS ((size_t)NROWS * D_MODEL)        // 8388608
#define W_ELEMS ((size_t)D_MODEL * D_MODEL)      // 4194304
#define QKV_ELEMS ((size_t)BATCH * NHEADS * S_LEN * HDIM)   // 8388608

// ------------------------- scratch (device globals) -------------------------
__device__ __nv_bfloat16 g_xh[X_ELEMS], g_xl[X_ELEMS];
__device__ __nv_bfloat16 g_wh[4 * W_ELEMS], g_wl[4 * W_ELEMS]; // q,k,v,o
__device__ __nv_bfloat16 g_qh[QKV_ELEMS], g_ql[QKV_ELEMS];     // [bh][s][dh]
__device__ __nv_bfloat16 g_kh[QKV_ELEMS], g_kl[QKV_ELEMS];
__device__ __nv_bfloat16 g_vh[QKV_ELEMS], g_vl[QKV_ELEMS];
__device__ __nv_bfloat16 g_ah[X_ELEMS], g_al[X_ELEMS];         // [b*s][h*128+dh]

// ------------------------- common helpers ----------------------------------
__device__ __forceinline__ uint32_t smem_u32(const void* p) {
    uint32_t a;
    asm("{ .reg .u64 t; cvta.to.shared.u64 t, %1; cvt.u32.u64 %0, t; }"
        : "=r"(a) : "l"(p));
    return a;
}

__device__ __forceinline__ void cp_async16(uint32_t s, const void* g) {
    asm volatile("cp.async.ca.shared.global [%0], [%1], 16;"
                 :: "r"(s), "l"(g) : "memory");
}
#define CP_COMMIT() asm volatile("cp.async.commit_group;" ::: "memory")
#define CP_WAIT1()  asm volatile("cp.async.wait_group 1;" ::: "memory")

__device__ __forceinline__ void ldsm_x4(uint32_t* r, uint32_t addr) {
    asm volatile("ldmatrix.sync.aligned.m8n8.x4.shared.b16 {%0,%1,%2,%3}, [%4];"
                 : "=r"(r[0]), "=r"(r[1]), "=r"(r[2]), "=r"(r[3]) : "r"(addr));
}
__device__ __forceinline__ void ldsm_x2(uint32_t* r, uint32_t addr) {
    asm volatile("ldmatrix.sync.aligned.m8n8.x2.shared.b16 {%0,%1}, [%2];"
                 : "=r"(r[0]), "=r"(r[1]) : "r"(addr));
}
__device__ __forceinline__ void ldsm_x2t(uint32_t* r, uint32_t addr) {
    asm volatile("ldmatrix.sync.aligned.m8n8.x2.trans.shared.b16 {%0,%1}, [%2];"
                 : "=r"(r[0]), "=r"(r[1]) : "r"(addr));
}
__device__ __forceinline__ void mma16816(float* d, const uint32_t* a, const uint32_t* b) {
    asm volatile("mma.sync.aligned.m16n8k16.row.col.f32.bf16.bf16.f32 "
        "{%0,%1,%2,%3}, {%4,%5,%6,%7}, {%8,%9}, {%0,%1,%2,%3};"
        : "+f"(d[0]), "+f"(d[1]), "+f"(d[2]), "+f"(d[3])
        : "r"(a[0]), "r"(a[1]), "r"(a[2]), "r"(a[3]), "r"(b[0]), "r"(b[1]));
}

__device__ __forceinline__ void split1(float v, __nv_bfloat16& h, __nv_bfloat16& l) {
    h = __float2bfloat16(v);
    l = __float2bfloat16(v - __bfloat162float(h));
}
__device__ __forceinline__ uint32_t pack_bf16(__nv_bfloat16 a, __nv_bfloat16 b) {
    union { __nv_bfloat162 v; uint32_t u; } u;
    u.v = __nv_bfloat162(a, b);
    return u.u;
}

// ===================== mma.sync GEMM core (occ=2) ===========================
// 128x128 CTA tile, 256 threads = 8 warps in 2(m) x 4(n); warp tile 64x32.
// D += Ah*Bh + Al*Bh + Ah*Bl. cp.async double-buffered K=32.
#define MM_SA     40
#define MM_MAT    10240
#define MM_STAGE  40960
#define GEMM_SMEM_BYTES 81920

__device__ __forceinline__ void mm_issue(
        const __nv_bfloat16* __restrict__ Ah, const __nv_bfloat16* __restrict__ Al,
        const __nv_bfloat16* __restrict__ Bh, const __nv_bfloat16* __restrict__ Bl,
        uint32_t sbase, int k0) {
    #pragma unroll
    for (int i = 0; i < 2; i++) {
        const int idx = threadIdx.x + i * 256;
        const int row = idx >> 2, seg = idx & 3;
        const size_t go = (size_t)row * D_MODEL + k0 + seg * 8;
        const uint32_t so = sbase + (uint32_t)(row * MM_SA + seg * 8) * 2;
        cp_async16(so + 0 * MM_MAT, Ah + go);
        cp_async16(so + 1 * MM_MAT, Al + go);
        cp_async16(so + 2 * MM_MAT, Bh + go);
        cp_async16(so + 3 * MM_MAT, Bl + go);
    }
}

__device__ __forceinline__ void mm_compute(uint32_t sbase, float acc[4][4][4],
                                           int wm, int wn, int lane) {
    #pragma unroll
    for (int ks = 0; ks < 2; ks++) {
        uint32_t ah[4][4], al[4][4];
        const int acol = ks * 16 + (lane >> 4) * 8;
        #pragma unroll
        for (int mi = 0; mi < 4; mi++) {
            const int row = wm * 64 + mi * 16 + (lane & 15);
            const uint32_t off = (uint32_t)(row * MM_SA + acol) * 2;
            ldsm_x4(ah[mi], sbase + 0 * MM_MAT + off);
            ldsm_x4(al[mi], sbase + 1 * MM_MAT + off);
        }
        const int bcol = ks * 16 + ((lane >> 3) & 1) * 8;
        #pragma unroll
        for (int ni = 0; ni < 4; ni++) {
            uint32_t bh[2], bl[2];
            const int nrow = wn * 32 + ni * 8 + (lane & 7);
            const uint32_t off = (uint32_t)(nrow * MM_SA + bcol) * 2;
            ldsm_x2(bh, sbase + 2 * MM_MAT + off);
            ldsm_x2(bl, sbase + 3 * MM_MAT + off);
            #pragma unroll
            for (int mi = 0; mi < 4; mi++) {
                mma16816(acc[mi][ni], ah[mi], bh);
                mma16816(acc[mi][ni], al[mi], bh);
                mma16816(acc[mi][ni], ah[mi], bl);
            }
        }
    }
}

__device__ __forceinline__ void gemm_tile_mma(
        const __nv_bfloat16* __restrict__ Ah, const __nv_bfloat16* __restrict__ Al,
        const __nv_bfloat16* __restrict__ Bh, const __nv_bfloat16* __restrict__ Bl,
        uint32_t sb, float acc[4][4][4]) {
    const int lane = threadIdx.x & 31;
    const int wid = threadIdx.x >> 5;
    const int wm = wid >> 2, wn = wid & 3;

    mm_issue(Ah, Al, Bh, Bl, sb, 0);
    CP_COMMIT();
    for (int c = 0; c < D_MODEL / 32; c++) {
        if (c + 1 < D_MODEL / 32)
            mm_issue(Ah, Al, Bh, Bl, sb + ((c + 1) & 1) * MM_STAGE, (c + 1) * 32);
        CP_COMMIT();
        CP_WAIT1();
        __syncthreads();
        mm_compute(sb + (c & 1) * MM_STAGE, acc, wm, wn, lane);
        __syncthreads();
    }
}

// ------------------------------- QKV GEMM -----------------------------------
__global__ __launch_bounds__(256, 2) void qkv_tc_kernel() {
    extern __shared__ __align__(1024) char smem[];
    const uint32_t sb = smem_u32(smem);
    const int z = blockIdx.z;
    const int head = blockIdx.x;
    const int row0 = blockIdx.y * 128;

    const __nv_bfloat16* Ah = g_xh + (size_t)row0 * D_MODEL;
    const __nv_bfloat16* Al = g_xl + (size_t)row0 * D_MODEL;
    const __nv_bfloat16* Bh = g_wh + (size_t)z * W_ELEMS + (size_t)head * 128 * D_MODEL;
    const __nv_bfloat16* Bl = g_wl + (size_t)z * W_ELEMS + (size_t)head * 128 * D_MODEL;
    __nv_bfloat16* dsth = (z == 0) ? g_qh : (z == 1) ? g_kh : g_vh;
    __nv_bfloat16* dstl = (z == 0) ? g_ql : (z == 1) ? g_kl : g_vl;

    float acc[4][4][4];
    #pragma unroll
    for (int mi = 0; mi < 4; mi++)
        #pragma unroll
        for (int ni = 0; ni < 4; ni++)
            #pragma unroll
            for (int k = 0; k < 4; k++) acc[mi][ni][k] = 0.f;

    gemm_tile_mma(Ah, Al, Bh, Bl, sb, acc);

    const int lane = threadIdx.x & 31, wid = threadIdx.x >> 5;
    const int wm = wid >> 2, wn = wid & 3;
    #pragma unroll
    for (int mi = 0; mi < 4; mi++) {
        const int r0_ = row0 + wm * 64 + mi * 16 + (lane >> 2);
        #pragma unroll
        for (int rr = 0; rr < 2; rr++) {
            const int gr = r0_ + rr * 8;
            const int b = gr >> 11, s = gr & 2047;
            const size_t base = ((size_t)((b * NHEADS + head) * S_LEN + s)) << 7;
            #pragma unroll
            for (int ni = 0; ni < 4; ni++) {
                const int col = wn * 32 + ni * 8 + (lane & 3) * 2;
                __nv_bfloat16 h0, l0, h1, l1;
                split1(acc[mi][ni][rr * 2 + 0], h0, l0);
                split1(acc[mi][ni][rr * 2 + 1], h1, l1);
                *(uint32_t*)(dsth + base + col) = pack_bf16(h0, h1);
                *(uint32_t*)(dstl + base + col) = pack_bf16(l0, l1);
            }
        }
    }
}

// ------------------------------- OUT GEMM -----------------------------------
__global__ __launch_bounds__(256, 2) void out_tc_kernel(float* __restrict__ C) {
    extern __shared__ __align__(1024) char smem[];
    const uint32_t sb = smem_u32(smem);
    const int row0 = blockIdx.y * 128;
    const int col0 = blockIdx.x * 128;

    const __nv_bfloat16* Ah = g_ah + (size_t)row0 * D_MODEL;
    const __nv_bfloat16* Al = g_al + (size_t)row0 * D_MODEL;
    const __nv_bfloat16* Bh = g_wh + 3 * W_ELEMS + (size_t)col0 * D_MODEL;
    const __nv_bfloat16* Bl = g_wl + 3 * W_ELEMS + (size_t)col0 * D_MODEL;

    float acc[4][4][4];
    #pragma unroll
    for (int mi = 0; mi < 4; mi++)
        #pragma unroll
        for (int ni = 0; ni < 4; ni++)
            #pragma unroll
            for (int k = 0; k < 4; k++) acc[mi][ni][k] = 0.f;

    gemm_tile_mma(Ah, Al, Bh, Bl, sb, acc);

    const int lane = threadIdx.x & 31, wid = threadIdx.x >> 5;
    const int wm = wid >> 2, wn = wid & 3;
    #pragma unroll
    for (int mi = 0; mi < 4; mi++) {
        const int r0_ = row0 + wm * 64 + mi * 16 + (lane >> 2);
        #pragma unroll
        for (int rr = 0; rr < 2; rr++) {
            float* dst = C + (size_t)(r0_ + rr * 8) * D_MODEL + col0;
            #pragma unroll
            for (int ni = 0; ni < 4; ni++) {
                const int col = wn * 32 + ni * 8 + (lane & 3) * 2;
                *(float2*)(dst + col) =
                    make_float2(acc[mi][ni][rr * 2 + 0], acc[mi][ni][rr * 2 + 1]);
            }
        }
    }
}

// ---------------------------- bf16 split kernels ----------------------------
__global__ __launch_bounds__(256) void split_x_kernel(const float* __restrict__ src) {
    size_t i = ((size_t)blockIdx.x * 256 + threadIdx.x) * 4;
    float4 v = *(const float4*)(src + i);
    __nv_bfloat16 h[4], l[4];
    split1(v.x, h[0], l[0]); split1(v.y, h[1], l[1]);
    split1(v.z, h[2], l[2]); split1(v.w, h[3], l[3]);
    *(uint2*)(g_xh + i) = *(uint2*)h;
    *(uint2*)(g_xl + i) = *(uint2*)l;
}

__global__ __launch_bounds__(256) void split_w_kernel(const float* __restrict__ src, int which) {
    size_t i = ((size_t)blockIdx.x * 256 + threadIdx.x) * 4;
    float4 v = *(const float4*)(src + i);
    __nv_bfloat16 h[4], l[4];
    split1(v.x, h[0], l[0]); split1(v.y, h[1], l[1]);
    split1(v.z, h[2], l[2]); split1(v.w, h[3], l[3]);
    *(uint2*)(g_wh + (size_t)which * W_ELEMS + i) = *(uint2*)h;
    *(uint2*)(g_wl + (size_t)which * W_ELEMS + i) = *(uint2*)l;
}

// ======================= flash attention (mma.sync) =========================
// Block: 128 q-rows x one (b,h); 8 warps, each warp owns 16 q-rows.
// K-tiles of 64. Q[128x128] resident in smem; K,V row-major [64][136] hi/lo,
// cp.async double-buffered. V B-fragments via ldmatrix.trans (no transpose STS).
#define FQSTR 136
#define FKV   136
#define FOFF_QH 0
#define FOFF_QL (128 * FQSTR * 2)                 // 34816
#define FST0    (2 * 128 * FQSTR * 2)             // 69632
#define KH_OFF  0
#define KL_OFF  (64 * FKV * 2)                    // 17408
#define VH_OFF  (2 * 64 * FKV * 2)                // 34816
#define VL_OFF  (3 * 64 * FKV * 2)                // 52224
#define STG_SZ  (4 * 64 * FKV * 2)                // 69632
#define FLASH_SMEM_BYTES (FST0 + 2 * STG_SZ)      // 208896

__device__ __forceinline__ void flash_issue(uint32_t stg,
        const __nv_bfloat16* __restrict__ Khp, const __nv_bfloat16* __restrict__ Klp,
        const __nv_bfloat16* __restrict__ Vhp, const __nv_bfloat16* __restrict__ Vlp,
        int k0) {
    const int tid = threadIdx.x;
    #pragma unroll
    for (int i = 0; i < 4; i++) {
        const int idx = tid + i * 256;            // 0..1023
        const int r = idx >> 4, c8 = (idx & 15) * 8;
        const size_t go = (size_t)(k0 + r) * HDIM + c8;
        const uint32_t so = stg + (uint32_t)(r * FKV + c8) * 2;
        cp_async16(so + KH_OFF, Khp + go);
        cp_async16(so + KL_OFF, Klp + go);
        cp_async16(so + VH_OFF, Vhp + go);
        cp_async16(so + VL_OFF, Vlp + go);
    }
}

__global__ __launch_bounds__(256, 1) void flash_mma_kernel() {
    extern __shared__ __align__(1024) char smem[];
    const uint32_t sb = smem_u32(smem);
    const int tid = threadIdx.x;
    const int lane = tid & 31;
    const int w = tid >> 5;
    const int qblk = gridDim.x - 1 - blockIdx.x;   // heavy blocks first
    const int q0 = qblk * 128;
    const int bh = blockIdx.y;

    const __nv_bfloat16* Qhp = g_qh + ((size_t)bh * S_LEN + q0) * HDIM;
    const __nv_bfloat16* Qlp = g_ql + ((size_t)bh * S_LEN + q0) * HDIM;
    const __nv_bfloat16* Khp = g_kh + (size_t)bh * S_LEN * HDIM;
    const __nv_bfloat16* Klp = g_kl + (size_t)bh * S_LEN * HDIM;
    const __nv_bfloat16* Vhp = g_vh + (size_t)bh * S_LEN * HDIM;
    const __nv_bfloat16* Vlp = g_vl + (size_t)bh * S_LEN * HDIM;

    // Q tile (128x128) hi/lo into padded smem
    #pragma unroll
    for (int i = 0; i < 8; i++) {
        const int idx = tid + i * 256;              // 0..2047
        const int r = idx >> 4, c8 = (idx & 15) * 8;
        const uint32_t so = (uint32_t)(r * FQSTR + c8) * 2;
        *(uint4*)(smem + FOFF_QH + so) = *(const uint4*)(Qhp + (size_t)r * HDIM + c8);
        *(uint4*)(smem + FOFF_QL + so) = *(const uint4*)(Qlp + (size_t)r * HDIM + c8);
    }

    const float NEG_INF = __int_as_float(0xff800000);
    const float qsc = 0.08838834764831845f;         // 1/sqrt(128)
    float m0 = NEG_INF, m1 = NEG_INF, l0 = 0.f, l1 = 0.f;
    float O[16][4];
    #pragma unroll
    for (int j = 0; j < 16; j++)
        #pragma unroll
        for (int k = 0; k < 4; k++) O[j][k] = 0.f;

    const int ntiles = 2 * (qblk + 1);
    flash_issue(sb + FST0, Khp, Klp, Vhp, Vlp, 0);
    CP_COMMIT();

    for (int t = 0; t < ntiles; t++) {
        const int k0 = t * 64;
        if (t + 1 < ntiles)
            flash_issue(sb + FST0 + ((t + 1) & 1) * STG_SZ, Khp, Klp, Vhp, Vlp,
                        (t + 1) * 64);
        CP_COMMIT();
        CP_WAIT1();
        __syncthreads();                            // stage t ready (+ Q on t==0)
        const uint32_t stg = sb + FST0 + (t & 1) * STG_SZ;

        // ---- S = Q @ K^T (warp: 16 rows x 64 cols) ----
        float S[8][4];
        #pragma unroll
        for (int j = 0; j < 8; j++)
            #pragma unroll
            for (int k = 0; k < 4; k++) S[j][k] = 0.f;

        #pragma unroll
        for (int kt = 0; kt < 8; kt++) {
            uint32_t qa_h[4], qa_l[4];
            const int arow = w * 16 + (lane & 15);
            const int acol = kt * 16 + (lane >> 4) * 8;
            const uint32_t aoff = (uint32_t)(arow * FQSTR + acol) * 2;
            ldsm_x4(qa_h, sb + FOFF_QH + aoff);
            ldsm_x4(qa_l, sb + FOFF_QL + aoff);
            const int bcol = kt * 16 + ((lane >> 3) & 1) * 8;
            #pragma unroll
            for (int j = 0; j < 8; j++) {
                uint32_t kb_h[2], kb_l[2];
                const int nrow = j * 8 + (lane & 7);
                const uint32_t boff = (uint32_t)(nrow * FKV + bcol) * 2;
                ldsm_x2(kb_h, stg + KH_OFF + boff);
                ldsm_x2(kb_l, stg + KL_OFF + boff);
                mma16816(S[j], qa_h, kb_h);
                mma16816(S[j], qa_l, kb_h);
                mma16816(S[j], qa_h, kb_l);
            }
        }

        // scale + causal mask (only diagonal-touching tiles)
        const int row0g = q0 + w * 16 + (lane >> 2);
        const int row1g = row0g + 8;
        if (k0 + 63 > q0) {
            #pragma unroll
            for (int j = 0; j < 8; j++) {
                const int colg = k0 + j * 8 + (lane & 3) * 2;
                S[j][0] = (colg     > row0g) ? NEG_INF : S[j][0] * qsc;
                S[j][1] = (colg + 1 > row0g) ? NEG_INF : S[j][1] * qsc;
                S[j][2] = (colg     > row1g) ? NEG_INF : S[j][2] * qsc;
                S[j][3] = (colg + 1 > row1g) ? NEG_INF : S[j][3] * qsc;
            }
        } else {
            #pragma unroll
            for (int j = 0; j < 8; j++) {
                S[j][0] *= qsc; S[j][1] *= qsc; S[j][2] *= qsc; S[j][3] *= qsc;
            }
        }

        // ---- online softmax (rows r0 = lane>>2, r1 = r0+8) ----
        float mx0 = m0, mx1 = m1;
        #pragma unroll
        for (int j = 0; j < 8; j++) {
            mx0 = fmaxf(mx0, fmaxf(S[j][0], S[j][1]));
            mx1 = fmaxf(mx1, fmaxf(S[j][2], S[j][3]));
        }
        mx0 = fmaxf(mx0, __shfl_xor_sync(0xffffffff, mx0, 1));
        mx0 = fmaxf(mx0, __shfl_xor_sync(0xffffffff, mx0, 2));
        mx1 = fmaxf(mx1, __shfl_xor_sync(0xffffffff, mx1, 1));
        mx1 = fmaxf(mx1, __shfl_xor_sync(0xffffffff, mx1, 2));

        const float sc0 = __expf(m0 - mx0);   // 0 when m0 == -inf
        const float sc1 = __expf(m1 - mx1);
        m0 = mx0; m1 = mx1;

        float rs0 = 0.f, rs1 = 0.f;
        #pragma unroll
        for (int j = 0; j < 8; j++) {
            S[j][0] = __expf(S[j][0] - mx0);
            S[j][1] = __expf(S[j][1] - mx0);
            S[j][2] = __expf(S[j][2] - mx1);
            S[j][3] = __expf(S[j][3] - mx1);
            rs0 += S[j][0] + S[j][1];
            rs1 += S[j][2] + S[j][3];
        }
        rs0 += __shfl_xor_sync(0xffffffff, rs0, 1);
        rs0 += __shfl_xor_sync(0xffffffff, rs0, 2);
        rs1 += __shfl_xor_sync(0xffffffff, rs1, 1);
        rs1 += __shfl_xor_sync(0xffffffff, rs1, 2);
        l0 = l0 * sc0 + rs0;
        l1 = l1 * sc1 + rs1;

        #pragma unroll
        for (int j = 0; j < 16; j++) {
            O[j][0] *= sc0; O[j][1] *= sc0; O[j][2] *= sc1; O[j][3] *= sc1;
        }

        // ---- P fragments (hi/lo) from S accumulators ----
        uint32_t pa_h[4][4], pa_l[4][4];
        #pragma unroll
        for (int pt = 0; pt < 4; pt++) {
            #pragma unroll
            for (int q = 0; q < 4; q++) {
                const int jj = pt * 2 + (q >> 1);
                const int e0 = (q & 1) * 2;
                __nv_bfloat16 h0, L0, h1, L1;
                split1(S[jj][e0 + 0], h0, L0);
                split1(S[jj][e0 + 1], h1, L1);
                pa_h[pt][q] = pack_bf16(h0, h1);
                pa_l[pt][q] = pack_bf16(L0, L1);
            }
        }

        // ---- O += P @ V : V B-fragments via ldmatrix.trans from [s][dh] ----
        #pragma unroll
        for (int pt = 0; pt < 4; pt++) {
            const int krow = pt * 16 + (lane & 15);
            #pragma unroll
            for (int j = 0; j < 16; j++) {
                uint32_t vb_h[2], vb_l[2];
                const uint32_t boff = (uint32_t)(krow * FKV + j * 8) * 2;
                ldsm_x2t(vb_h, stg + VH_OFF + boff);
                ldsm_x2t(vb_l, stg + VL_OFF + boff);
                mma16816(O[j], pa_h[pt], vb_h);
                mma16816(O[j], pa_l[pt], vb_h);
                mma16816(O[j], pa_h[pt], vb_l);
            }
        }
        __syncthreads();                            // done with stage t smem
    }

    // ---- epilogue: normalize, write bf16 hi/lo into g_ah/g_al ----
    const float inv0 = 1.0f / l0;
    const float inv1 = 1.0f / l1;
    const int b = bh >> 4, h = bh & 15;
    const int s0 = q0 + w * 16 + (lane >> 2);
    const size_t base0 = (size_t)(b * S_LEN + s0) * D_MODEL + h * HDIM;
    const size_t base1 = (size_t)(b * S_LEN + s0 + 8) * D_MODEL + h * HDIM;
    #pragma unroll
    for (int j = 0; j < 16; j++) {
        const int col = j * 8 + (lane & 3) * 2;
        __nv_bfloat16 h0, L0, h1, L1;
        split1(O[j][0] * inv0, h0, L0);
        split1(O[j][1] * inv0, h1, L1);
        *(uint32_t*)(g_ah + base0 + col) = pack_bf16(h0, h1);
        *(uint32_t*)(g_al + base0 + col) = pack_bf16(L0, L1);
        split1(O[j][2] * inv1, h0, L0);
        split1(O[j][3] * inv1, h1, L1);
        *(uint32_t*)(g_ah + base1 + col) = pack_bf16(h0, h1);
        *(uint32_t*)(g_al + base1 + col) = pack_bf16(L0, L1);
    }
}

// ---------------------------------------------------------------------------
extern "C" void kernel_launch(void* const* d_in, const int* in_sizes, int n_in,
                              void* d_out, int out_size) {
    const float* x  = (const float*)d_in[0];
    const float* wq = (const float*)d_in[1];
    const float* wk = (const float*)d_in[2];
    const float* wv = (const float*)d_in[3];
    const float* wo = (const float*)d_in[4];
    float* out = (float*)d_out;

    cudaFuncSetAttribute(qkv_tc_kernel, cudaFuncAttributeMaxDynamicSharedMemorySize,
                         GEMM_SMEM_BYTES);
    cudaFuncSetAttribute(out_tc_kernel, cudaFuncAttributeMaxDynamicSharedMemorySize,
                         GEMM_SMEM_BYTES);
    cudaFuncSetAttribute(flash_mma_kernel, cudaFuncAttributeMaxDynamicSharedMemorySize,
                         FLASH_SMEM_BYTES);

    split_x_kernel<<<(unsigned)(X_ELEMS / 4 / 256), 256>>>(x);
    split_w_kernel<<<(unsigned)(W_ELEMS / 4 / 256), 256>>>(wq, 0);
    split_w_kernel<<<(unsigned)(W_ELEMS / 4 / 256), 256>>>(wk, 1);
    split_w_kernel<<<(unsigned)(W_ELEMS / 4 / 256), 256>>>(wv, 2);
    split_w_kernel<<<(unsigned)(W_ELEMS / 4 / 256), 256>>>(wo, 3);

    qkv_tc_kernel<<<dim3(D_MODEL / 128, NROWS / 128, 3), 256, GEMM_SMEM_BYTES>>>();
    flash_mma_kernel<<<dim3(S_LEN / 128, BATCH * NHEADS), 256, FLASH_SMEM_BYTES>>>();
    out_tc_kernel<<<dim3(D_MODEL / 128, NROWS / 128), 256, GEMM_SMEM_BYTES>>>(out);
}